// round 10
// baseline (speedup 1.0000x reference)
#include <cuda_runtime.h>
#include <cuda_bf16.h>
#include <math.h>
#include <cstdint>

// ---------------- problem constants ----------------
#define PB 256
#define PN 128
#define PD 768
#define PE 3
#define PS 44
#define PES 132
#define PESP 136          // padded combine ld
#define PMUP 144          // padded mu_cat ld
#define PH 1024
#define PMAXS 88
#define PM_TOK (PB*PN)
#define PM_FFN (PB*PS)

// ---------------- scratch (device globals) ----------------
__device__ float g_slot_input[PB * 769];
__device__ float g_slot_bias [PB * PD];
__device__ float g_img_n     [PM_TOK * PD];
__device__ float g_dot       [PM_TOK];
__device__ float g_mu_cat    [PD * PMUP];
__device__ float g_logits    [PM_TOK * PES];
__device__ float g_dispT     [PB * PES * PN];     // (b, 132, 128)
__device__ float g_combine   [PM_TOK * PESP];     // padded ld 136
__device__ float g_slot_in   [PB * PES * PD];
__device__ float g_hbuf      [PB * PES * PH];
__device__ float g_slot_out  [PB * PES * PD];
__device__ float g_cls_h     [PB * 4 * PD];

// ---------------- helpers ----------------
__device__ __forceinline__ float gelu_exact(float x) {
    return 0.5f * x * (1.0f + erff(x * 0.70710678118654752440f));
}
__device__ __forceinline__ unsigned long long bcast2(float x) {
    unsigned long long r;
    asm("mov.b64 %0, {%1, %1};" : "=l"(r) : "r"(__float_as_uint(x)));
    return r;
}
__device__ __forceinline__ void ffma2(unsigned long long& c,
                                      unsigned long long a,
                                      unsigned long long b) {
    asm("fma.rn.f32x2 %0, %1, %2, %0;" : "+l"(c) : "l"(a), "l"(b));
}
__device__ __forceinline__ uint32_t smem_u32(const void* p) {
    uint32_t a;
    asm("{ .reg .u64 t; cvta.to.shared.u64 t, %1; cvt.u32.u64 %0, t; }" : "=r"(a) : "l"(p));
    return a;
}
__device__ __forceinline__ void cp_async16(uint32_t dst, const void* src) {
    asm volatile("cp.async.cg.shared.global [%0], [%1], 16;" :: "r"(dst), "l"(src));
}
#define CP_COMMIT() asm volatile("cp.async.commit_group;" ::: "memory")
#define CP_WAIT0()  asm volatile("cp.async.wait_group 0;" ::: "memory")

// ---- tf32 helpers (tensor path) ----
__device__ __forceinline__ unsigned f2tf(float x) {
    unsigned u; asm("cvt.rna.tf32.f32 %0, %1;" : "=r"(u) : "f"(x)); return u;
}
__device__ __forceinline__ void split_tf(float x, unsigned& hi, unsigned& lo) {
    hi = f2tf(x);
    lo = f2tf(x - __uint_as_float(hi));
}
__device__ __forceinline__ void mma8(float* c, const unsigned* a, const unsigned* b) {
    asm volatile(
      "mma.sync.aligned.m16n8k8.row.col.f32.tf32.tf32.f32 "
      "{%0,%1,%2,%3}, {%4,%5,%6,%7}, {%8,%9}, {%0,%1,%2,%3};"
      : "+f"(c[0]), "+f"(c[1]), "+f"(c[2]), "+f"(c[3])
      : "r"(a[0]), "r"(a[1]), "r"(a[2]), "r"(a[3]), "r"(b[0]), "r"(b[1]));
}

#define EP_STORE     0
#define EP_BIAS      1
#define EP_BIAS_GELU 2
#define EP_LOGITS    3

// ---------------- tensor (3xTF32 mma) block path ----------------
// Unguarded: full 128x128 tile, K % 16 == 0, aligned rows.
template<bool MAP_ROWS, int EP>
__device__ void tensor_block(char* sm,
    const float* __restrict__ Ab, const float* __restrict__ Bb, float* __restrict__ Cb,
    int K, int lda, int ldb, int ldc, int m0, int n0, int z,
    const float* __restrict__ v1, int biasStride)
{
    // fragment-permuted smem planes (verified layout from 3xTF32 round):
    unsigned (*AsH)[8][128] = reinterpret_cast<unsigned(*)[8][128]>(sm);
    unsigned (*AsL)[8][128] = reinterpret_cast<unsigned(*)[8][128]>(sm + 8192);
    unsigned (*BsH)[16][64] = reinterpret_cast<unsigned(*)[16][64]>(sm + 16384);
    unsigned (*BsL)[16][64] = reinterpret_cast<unsigned(*)[16][64]>(sm + 24576);

    const int tid  = threadIdx.x;
    const int lane = tid & 31;
    const int wid  = tid >> 5;
    const int wm   = wid & 1;     // 2 warps in M (64 rows each)
    const int wn   = wid >> 1;    // 4 warps in N (32 cols each)

    float acc[4][4][4];
    #pragma unroll
    for (int i = 0; i < 4; i++)
        #pragma unroll
        for (int j = 0; j < 4; j++)
            #pragma unroll
            for (int q = 0; q < 4; q++) acc[i][j][q] = 0.f;

    const int arow  = tid >> 1;
    const int ahalf = (tid & 1) * 8;
    const int t_k = tid >> 4;
    const int t_c = (tid & 15) * 8;

    int amr = m0 + arow;
    if (MAP_ROWS) amr = ((m0 + arow) / 44) * PES + z * PS + ((m0 + arow) % 44);
    const long long a_off = (long long)amr * lda;

    const int nk = K >> 4;
    for (int kt = 0; kt < nk; kt++) {
        const int k0 = kt << 4;
        float av[8], bv[8];
        {
            const float4 u0 = *reinterpret_cast<const float4*>(Ab + a_off + k0 + ahalf);
            const float4 u1 = *reinterpret_cast<const float4*>(Ab + a_off + k0 + ahalf + 4);
            av[0]=u0.x; av[1]=u0.y; av[2]=u0.z; av[3]=u0.w;
            av[4]=u1.x; av[5]=u1.y; av[6]=u1.z; av[7]=u1.w;
        }
        {
            const long long ro = (long long)(k0 + t_k) * ldb + n0 + t_c;
            const float4 u0 = *reinterpret_cast<const float4*>(Bb + ro);
            const float4 u1 = *reinterpret_cast<const float4*>(Bb + ro + 4);
            bv[0]=u0.x; bv[1]=u0.y; bv[2]=u0.z; bv[3]=u0.w;
            bv[4]=u1.x; bv[5]=u1.y; bv[6]=u1.z; bv[7]=u1.w;
        }
        __syncthreads();   // previous compute finished
        #pragma unroll
        for (int j = 0; j < 8; j++) {
            const int kl = ahalf + j;
            const int kb = kl >> 3, kk = kl & 7;
            const int mt = arow >> 4, rq = arow & 15;
            const int idx = ((rq & 7) * 4 + (kk & 3)) * 4 + ((kk >> 2) * 2 + (rq >> 3));
            unsigned h, l;
            split_tf(av[j], h, l);
            AsH[kb][mt][idx] = h;
            AsL[kb][mt][idx] = l;
        }
        {
            const int kb = t_k >> 3, kk = t_k & 7;
            const int c = kk & 3, pr = kk >> 2;
            #pragma unroll
            for (int j = 0; j < 8; j++) {
                const int nidx = t_c + j;
                const int idx = ((nidx & 7) * 4 + c) * 2 + pr;
                unsigned h, l;
                split_tf(bv[j], h, l);
                BsH[kb][nidx >> 3][idx] = h;
                BsL[kb][nidx >> 3][idx] = l;
            }
        }
        __syncthreads();
        #pragma unroll
        for (int kb = 0; kb < 2; kb++) {
            uint4 afH[4], afL[4];
            uint2 bfH[4], bfL[4];
            #pragma unroll
            for (int mt = 0; mt < 4; mt++) {
                afH[mt] = *reinterpret_cast<const uint4*>(&AsH[kb][wm * 4 + mt][lane * 4]);
                afL[mt] = *reinterpret_cast<const uint4*>(&AsL[kb][wm * 4 + mt][lane * 4]);
            }
            #pragma unroll
            for (int nt = 0; nt < 4; nt++) {
                bfH[nt] = *reinterpret_cast<const uint2*>(&BsH[kb][wn * 4 + nt][lane * 2]);
                bfL[nt] = *reinterpret_cast<const uint2*>(&BsL[kb][wn * 4 + nt][lane * 2]);
            }
            #pragma unroll
            for (int mt = 0; mt < 4; mt++)
                #pragma unroll
                for (int nt = 0; nt < 4; nt++) {
                    float* c = acc[mt][nt];
                    mma8(c, reinterpret_cast<const unsigned*>(&afL[mt]),
                            reinterpret_cast<const unsigned*>(&bfH[nt]));
                    mma8(c, reinterpret_cast<const unsigned*>(&afH[mt]),
                            reinterpret_cast<const unsigned*>(&bfL[nt]));
                    mma8(c, reinterpret_cast<const unsigned*>(&afH[mt]),
                            reinterpret_cast<const unsigned*>(&bfH[nt]));
                }
        }
    }

    const int lr = lane >> 2;
    const int lc = (lane & 3) * 2;
    #pragma unroll
    for (int mt = 0; mt < 4; mt++) {
        #pragma unroll
        for (int h = 0; h < 2; h++) {
            const int gm = m0 + wm * 64 + mt * 16 + lr + h * 8;
            int rr = gm;
            if (MAP_ROWS) rr = (gm / 44) * PES + z * PS + (gm % 44);
            float* crow = Cb + (long long)rr * ldc;
            #pragma unroll
            for (int nt = 0; nt < 4; nt++) {
                #pragma unroll
                for (int jj = 0; jj < 2; jj++) {
                    const int gn = n0 + wn * 32 + nt * 8 + lc + jj;
                    float v = acc[mt][nt][h * 2 + jj];
                    if (EP == EP_BIAS)           v += v1[z * biasStride + gn];
                    else if (EP == EP_BIAS_GELU) v = gelu_exact(v + v1[z * biasStride + gn]);
                    crow[gn] = v;
                }
            }
        }
    }
}

// ---------------- hybrid GEMM: FFMA2 blocks + tensor (mma) blocks ----------------
// C[M,N] = A[M,K] @ B[K,N] row-major; batch via blockIdx.z strides.
// MAP_ROWS: row m -> (m/44)*132 + z*44 + m%44 on A & C (expert slicing).
// Blocks with blockIdx.y >= tensor_y0 use the 3xTF32 mma path (unguarded only).
template<bool GUARD, bool MAP_ROWS, int EP>
__global__ __launch_bounds__(256)
void fgemm2(const float* __restrict__ A, const float* __restrict__ B,
            float* __restrict__ C,
            int M, int N, int K, int lda, int ldb, int ldc,
            long long sA, long long sB, long long sC,
            const float* __restrict__ v1, const float* __restrict__ v2,
            const float* __restrict__ scale_ptr, int biasStride,
            int tensor_y0)
{
    __shared__ __align__(16) char sm[32768];

    const int z = blockIdx.z;
    const float* Ab = A + (long long)z * sA;
    const float* Bb = B + (long long)z * sB;
    float*       Cb = C + (long long)z * sC;
    const int m0 = blockIdx.x * 128;
    const int n0 = blockIdx.y * 128;

    if (!GUARD && (int)blockIdx.y >= tensor_y0) {
        tensor_block<MAP_ROWS, EP>(sm, Ab, Bb, Cb, K, lda, ldb, ldc, m0, n0, z, v1, biasStride);
        return;
    }

    float (*As)[16][128] = reinterpret_cast<float(*)[16][128]>(sm);
    float (*Bs)[16][128] = reinterpret_cast<float(*)[16][128]>(sm + 16384);

    const int tid = threadIdx.x;          // 256
    const int tx = tid & 15;
    const int ty = tid >> 4;

    unsigned long long acc[8][4];
    #pragma unroll
    for (int i = 0; i < 8; i++)
        #pragma unroll
        for (int p = 0; p < 4; p++) acc[i][p] = 0ull;

    const int a_r  = tid >> 1;
    const int a_c8 = (tid & 1) * 8;
    const int t_k = tid >> 4;
    const int t_c = (tid & 15) * 8;

    long long a_off = 0;
    bool a_ok = true;
    {
        const int gm = m0 + a_r;
        a_ok = !GUARD || (gm < M);
        int rr = gm;
        if (MAP_ROWS) rr = (gm / 44) * PES + z * PS + (gm % 44);
        a_off = (long long)rr * lda;
    }
    const bool aAlign = ((a_off & 3) == 0);
    const bool bColsOk = !GUARD || (n0 + 128 <= N);

    const uint32_t bsu0 = smem_u32(&Bs[0][t_k][t_c]);
    const uint32_t bsu1 = smem_u32(&Bs[1][t_k][t_c]);

    const int nk = (K + 15) >> 4;
    float va[8], vb[8];

    auto load_a = [&](int kt) {
        const int k0 = kt << 4;
        const bool kfull = !GUARD || (k0 + 16 <= K);
        if ((!GUARD) || (a_ok && aAlign && kfull)) {
            const float4 u0 = *reinterpret_cast<const float4*>(Ab + a_off + k0 + a_c8);
            const float4 u1 = *reinterpret_cast<const float4*>(Ab + a_off + k0 + a_c8 + 4);
            va[0]=u0.x; va[1]=u0.y; va[2]=u0.z; va[3]=u0.w;
            va[4]=u1.x; va[5]=u1.y; va[6]=u1.z; va[7]=u1.w;
        } else {
            #pragma unroll
            for (int j = 0; j < 8; j++) {
                const int k = k0 + a_c8 + j;
                va[j] = (a_ok && k < K) ? Ab[a_off + k] : 0.f;
            }
        }
    };
    auto store_a = [&](int buf) {
        #pragma unroll
        for (int j = 0; j < 8; j++) As[buf][a_c8 + j][a_r] = va[j];
    };
    auto load_b_guard = [&](int kt) {
        const int k0 = kt << 4;
        const int gk = k0 + t_k;
        const long long ro = (long long)gk * ldb + n0 + t_c;
        if ((gk < K) && bColsOk && ((ro & 3) == 0)) {
            const float4 u0 = *reinterpret_cast<const float4*>(Bb + ro);
            const float4 u1 = *reinterpret_cast<const float4*>(Bb + ro + 4);
            vb[0]=u0.x; vb[1]=u0.y; vb[2]=u0.z; vb[3]=u0.w;
            vb[4]=u1.x; vb[5]=u1.y; vb[6]=u1.z; vb[7]=u1.w;
        } else {
            #pragma unroll
            for (int j = 0; j < 8; j++) {
                const int gn = n0 + t_c + j;
                vb[j] = (gk < K && gn < N) ? Bb[(long long)gk * ldb + gn] : 0.f;
            }
        }
    };
    auto store_b_guard = [&](int buf) {
        *reinterpret_cast<float4*>(&Bs[buf][t_k][t_c])     = make_float4(vb[0], vb[1], vb[2], vb[3]);
        *reinterpret_cast<float4*>(&Bs[buf][t_k][t_c + 4]) = make_float4(vb[4], vb[5], vb[6], vb[7]);
    };
    auto cp_b = [&](int kt, int buf) {
        const int gk = (kt << 4) + t_k;
        const float* src = Bb + (long long)gk * ldb + n0 + t_c;
        const uint32_t d = buf ? bsu1 : bsu0;
        cp_async16(d, src);
        cp_async16(d + 16, src + 4);
    };

    // ---- prologue: tile 0 ----
    load_a(0);
    if (GUARD) {
        load_b_guard(0);
        store_a(0);
        store_b_guard(0);
    } else {
        cp_b(0, 0);
        CP_COMMIT();
        store_a(0);
        CP_WAIT0();
    }
    __syncthreads();

    for (int kt = 0; kt < nk; kt++) {
        const int cur = kt & 1;
        const bool more = (kt + 1 < nk);
        if (more) {
            if (!GUARD) { cp_b(kt + 1, cur ^ 1); CP_COMMIT(); }
            else load_b_guard(kt + 1);
            load_a(kt + 1);
        }
        // ---- compute from buf cur, register-pipelined fragments ----
        float4 ca0 = *reinterpret_cast<const float4*>(&As[cur][0][ty * 8]);
        float4 ca1 = *reinterpret_cast<const float4*>(&As[cur][0][ty * 8 + 4]);
        ulonglong2 cbl = *reinterpret_cast<const ulonglong2*>(&Bs[cur][0][tx * 4]);
        ulonglong2 cbh = *reinterpret_cast<const ulonglong2*>(&Bs[cur][0][64 + tx * 4]);
        #pragma unroll
        for (int k = 0; k < 16; k++) {
            const int kn = (k + 1) & 15;
            const float4 na0 = *reinterpret_cast<const float4*>(&As[cur][kn][ty * 8]);
            const float4 na1 = *reinterpret_cast<const float4*>(&As[cur][kn][ty * 8 + 4]);
            const ulonglong2 nbl = *reinterpret_cast<const ulonglong2*>(&Bs[cur][kn][tx * 4]);
            const ulonglong2 nbh = *reinterpret_cast<const ulonglong2*>(&Bs[cur][kn][64 + tx * 4]);
            const float av[8] = {ca0.x, ca0.y, ca0.z, ca0.w, ca1.x, ca1.y, ca1.z, ca1.w};
            #pragma unroll
            for (int i = 0; i < 8; i++) {
                const unsigned long long ap = bcast2(av[i]);
                ffma2(acc[i][0], ap, cbl.x);
                ffma2(acc[i][1], ap, cbl.y);
                ffma2(acc[i][2], ap, cbh.x);
                ffma2(acc[i][3], ap, cbh.y);
            }
            ca0 = na0; ca1 = na1; cbl = nbl; cbh = nbh;
        }
        if (more) {
            store_a(cur ^ 1);
            if (GUARD) store_b_guard(cur ^ 1);
            else CP_WAIT0();
            __syncthreads();
        }
    }

    // ---- epilogue ----
    #pragma unroll
    for (int i = 0; i < 8; i++) {
        const int gm = m0 + ty * 8 + i;
        if (GUARD && gm >= M) continue;
        int rr = gm;
        if (MAP_ROWS) rr = (gm / 44) * PES + z * PS + (gm % 44);
        float dd = 0.f, sc = 0.f; int sel = 0;
        if (EP == EP_LOGITS) {
            const float w = v1[gm];
            sel = (w > 0.7f) ? 0 : ((w >= 0.3f) ? 1 : 2);
            dd = v2[gm];
            sc = scale_ptr[0];
        }
        float* crow = Cb + (long long)rr * ldc;
        #pragma unroll
        for (int p = 0; p < 4; p++) {
            const int gn0 = n0 + ((p < 2) ? (tx * 4 + p * 2) : (64 + tx * 4 + (p - 2) * 2));
            const uint2 u = *reinterpret_cast<const uint2*>(&acc[i][p]);
            #pragma unroll
            for (int h = 0; h < 2; h++) {
                const int gn = gn0 + h;
                if (GUARD && gn >= N) continue;
                float v = __uint_as_float(h ? u.y : u.x);
                if (EP == EP_BIAS) {
                    v += v1[z * biasStride + gn];
                } else if (EP == EP_BIAS_GELU) {
                    v = gelu_exact(v + v1[z * biasStride + gn]);
                } else if (EP == EP_LOGITS) {
                    v = ((gn / PS) == sel) ? sc * (v + dd) : 0.f;
                }
                crow[gn] = v;
            }
        }
    }
}

// ---------------- mu rearrange (padded ld 144) ----------------
__global__ void k_prep_mu(const float* __restrict__ mu, float* __restrict__ mu_cat) {
    int idx = blockIdx.x * blockDim.x + threadIdx.x;
    if (idx >= PD * PES) return;
    int d = idx / PES, j = idx % PES;
    int e = j / PS, s = j % PS;
    mu_cat[d * PMUP + j] = mu[((long long)e * PD + d) * PMAXS + s];
}

// ---------------- slot_input = [cls, mean(attn)] ----------------
__global__ void k_build_slotinput(const float* __restrict__ x,
                                  const float* __restrict__ attn,
                                  float* __restrict__ si) {
    int b = blockIdx.x;
    int t = threadIdx.x;
    __shared__ float red[8];
    float s = (t < PN) ? attn[b * PN + t] : 0.f;
    for (int o = 16; o; o >>= 1) s += __shfl_xor_sync(~0u, s, o);
    if ((t & 31) == 0) red[t >> 5] = s;
    __syncthreads();
    const float* cls = x + (long long)b * 129 * PD;
    float* o = si + (long long)b * 769;
    for (int d = t; d < PD; d += 256) o[d] = cls[d];
    if (t == 0) {
        float m = 0.f;
        #pragma unroll
        for (int i = 0; i < 8; i++) m += red[i];
        o[PD] = m * (1.f / (float)PN);
    }
}

// ---------------- LayerNorm + dot ----------------
__global__ void k_ln_dot(const float* __restrict__ x,
                         const float* __restrict__ gamma,
                         const float* __restrict__ beta,
                         const float* __restrict__ slot_bias,
                         float* __restrict__ img_n,
                         float* __restrict__ dot) {
    const int m = blockIdx.x;
    const int b = m >> 7;
    const int n = m & 127;
    const float* row = x + ((long long)b * 129 + 1 + n) * PD;
    const int t = threadIdx.x;
    const int w = t >> 5, l = t & 31;
    __shared__ float rs[8], rq[8];

    float v[3], s = 0.f, sq = 0.f;
    #pragma unroll
    for (int i = 0; i < 3; i++) {
        v[i] = row[t + i * 256];
        s += v[i];
        sq += v[i] * v[i];
    }
    for (int o = 16; o; o >>= 1) {
        s  += __shfl_xor_sync(~0u, s, o);
        sq += __shfl_xor_sync(~0u, sq, o);
    }
    if (l == 0) { rs[w] = s; rq[w] = sq; }
    __syncthreads();
    float ts = 0.f, tq = 0.f;
    #pragma unroll
    for (int i = 0; i < 8; i++) { ts += rs[i]; tq += rq[i]; }
    const float mean = ts * (1.f / (float)PD);
    const float var  = tq * (1.f / (float)PD) - mean * mean;
    const float inv  = rsqrtf(var + 1e-5f);
    __syncthreads();

    const float* sb = slot_bias + (long long)b * PD;
    float* orow = img_n + (long long)m * PD;
    float dp = 0.f;
    #pragma unroll
    for (int i = 0; i < 3; i++) {
        const int d = t + i * 256;
        const float y = (v[i] - mean) * inv * gamma[d] + beta[d];
        orow[d] = y;
        dp += y * sb[d];
    }
    for (int o = 16; o; o >>= 1) dp += __shfl_xor_sync(~0u, dp, o);
    if (l == 0) rs[w] = dp;
    __syncthreads();
    if (t == 0) {
        float d2 = 0.f;
        #pragma unroll
        for (int i = 0; i < 8; i++) d2 += rs[i];
        dot[m] = d2;
    }
}

// ---------------- dispatch softmax -> transposed output ----------------
__global__ void k_dispatch(const float* __restrict__ logits, float* __restrict__ dispT) {
    const int be = blockIdx.x;
    const int b = be / PE, e = be % PE;
    __shared__ float tile[PN][PS];
    __shared__ float csum[PS];
    const int t = threadIdx.x;
    const float* base = logits + (long long)b * PN * PES + e * PS;
    for (int idx = t; idx < PN * PS; idx += 256) {
        const int n = idx / PS, j = idx % PS;
        tile[n][j] = base[(long long)n * PES + j];
    }
    __syncthreads();
    if (t < PS) {
        float mx = -1e30f;
        for (int n = 0; n < PN; n++) mx = fmaxf(mx, tile[n][t]);
        float sm = 0.f;
        for (int n = 0; n < PN; n++) {
            const float ev = expf(tile[n][t] - mx);
            tile[n][t] = ev;
            sm += ev;
        }
        csum[t] = sm;
    }
    __syncthreads();
    float* ob = dispT + (long long)b * PES * PN + (long long)e * PS * PN;
    for (int idx = t; idx < PN * PS; idx += 256) {
        const int j = idx >> 7, n = idx & 127;
        ob[j * PN + n] = tile[n][j] / csum[j];
    }
}

// ---------------- combine softmax (padded ld out) ----------------
__global__ void k_combine(const float* __restrict__ logits, float* __restrict__ comb) {
    const int row = blockIdx.x * 8 + (threadIdx.x >> 5);
    const int l = threadIdx.x & 31;
    if (row >= PM_TOK) return;
    const float* r = logits + (long long)row * PES;
    float vals[5], mx = -1e30f;
    #pragma unroll
    for (int i = 0; i < 5; i++) {
        const int j = l + i * 32;
        vals[i] = (j < PES) ? r[j] : -1e30f;
        mx = fmaxf(mx, vals[i]);
    }
    for (int o = 16; o; o >>= 1) mx = fmaxf(mx, __shfl_xor_sync(~0u, mx, o));
    float s = 0.f;
    #pragma unroll
    for (int i = 0; i < 5; i++) {
        const int j = l + i * 32;
        if (j < PES) { vals[i] = expf(vals[i] - mx); s += vals[i]; }
    }
    for (int o = 16; o; o >>= 1) s += __shfl_xor_sync(~0u, s, o);
    const float inv = 1.f / s;
    float* o = comb + (long long)row * PESP;
    #pragma unroll
    for (int i = 0; i < 5; i++) {
        const int j = l + i * 32;
        if (j < PES) o[j] = vals[i] * inv;
    }
}

// ---------------- launch ----------------
extern "C" void kernel_launch(void* const* d_in, const int* in_sizes, int n_in,
                              void* d_out, int out_size) {
    const float* x      = (const float*)d_in[0];
    const float* attn   = (const float*)d_in[1];
    const float* gamma  = (const float*)d_in[2];
    const float* beta   = (const float*)d_in[3];
    const float* vsg_w  = (const float*)d_in[4];
    const float* vsg_b  = (const float*)d_in[5];
    const float* mu     = (const float*)d_in[6];
    const float* scale  = (const float*)d_in[7];
    const float* w1     = (const float*)d_in[8];
    const float* b1     = (const float*)d_in[9];
    const float* w2     = (const float*)d_in[10];
    const float* b2     = (const float*)d_in[11];
    const float* cw1    = (const float*)d_in[12];
    const float* cb1    = (const float*)d_in[13];
    const float* cw2    = (const float*)d_in[14];
    const float* cb2    = (const float*)d_in[15];
    float* out = (float*)d_out;

    float *p_si, *p_sb, *p_imgn, *p_dot, *p_mu, *p_log, *p_dispT, *p_comb;
    float *p_sin, *p_h, *p_sout, *p_clsh;
    cudaGetSymbolAddress((void**)&p_si,    g_slot_input);
    cudaGetSymbolAddress((void**)&p_sb,    g_slot_bias);
    cudaGetSymbolAddress((void**)&p_imgn,  g_img_n);
    cudaGetSymbolAddress((void**)&p_dot,   g_dot);
    cudaGetSymbolAddress((void**)&p_mu,    g_mu_cat);
    cudaGetSymbolAddress((void**)&p_log,   g_logits);
    cudaGetSymbolAddress((void**)&p_dispT, g_dispT);
    cudaGetSymbolAddress((void**)&p_comb,  g_combine);
    cudaGetSymbolAddress((void**)&p_sin,   g_slot_in);
    cudaGetSymbolAddress((void**)&p_h,     g_hbuf);
    cudaGetSymbolAddress((void**)&p_sout,  g_slot_out);
    cudaGetSymbolAddress((void**)&p_clsh,  g_cls_h);

    // 1. mu -> (768, 144-padded 132)
    k_prep_mu<<<(PD * PES + 255) / 256, 256>>>(mu, p_mu);
    // 2. slot_input
    k_build_slotinput<<<PB, 256>>>(x, attn, p_si);
    // 3. slot_bias = slot_input @ vsg_w + vsg_b   (256,768,K=769)
    fgemm2<true, false, EP_BIAS><<<dim3(2, 6, 1), 256>>>(
        p_si, vsg_w, p_sb, PB, PD, 769, 769, PD, PD,
        0, 0, 0, vsg_b, nullptr, nullptr, 0, 9999);
    // 4. LayerNorm + dot
    k_ln_dot<<<PM_TOK, 256>>>(x, gamma, beta, p_sb, p_imgn, p_dot);
    // 5. logits (32768,132,K=768)
    fgemm2<true, false, EP_LOGITS><<<dim3(PM_TOK / 128, 2, 1), 256>>>(
        p_imgn, p_mu, p_log, PM_TOK, PES, PD, PD, PMUP, PES,
        0, 0, 0, attn, p_dot, scale, 0, 9999);
    // 6/7. softmaxes
    k_dispatch<<<PB * PE, 256>>>(p_log, p_dispT);
    k_combine<<<PM_TOK / 8, 256>>>(p_log, p_comb);
    // 8. slot_in[b] = dispT[b] @ img[b]   (132,768,K=128) batched
    fgemm2<true, false, EP_STORE><<<dim3(2, 6, PB), 256>>>(
        p_dispT, x + PD, p_sin, PES, PD, PN, PN, PD, PD,
        (long long)PES * PN, (long long)129 * PD, (long long)PES * PD,
        nullptr, nullptr, nullptr, 0, 9999);
    // 9. FFN1 (11264,1024,K=768) per expert — hybrid: y>=5 tensor (3 of 8 tiles)
    fgemm2<false, true, EP_BIAS_GELU><<<dim3(PM_FFN / 128, PH / 128, PE), 256>>>(
        p_sin, w1, p_h, PM_FFN, PH, PD, PD, PH, PH,
        0, (long long)PD * PH, 0, b1, nullptr, nullptr, PH, 5);
    // 10. FFN2 (11264,768,K=1024) per expert — hybrid: y>=4 tensor (2 of 6 tiles)
    fgemm2<false, true, EP_BIAS><<<dim3(PM_FFN / 128, PD / 128, PE), 256>>>(
        p_h, w2, p_sout, PM_FFN, PD, PH, PH, PD, PD,
        0, (long long)PH * PD, 0, b2, nullptr, nullptr, PD, 4);
    // 11. img_out[b] = combine[b] @ slot_out[b]  (128,768,K=132) batched
    fgemm2<true, false, EP_STORE><<<dim3(1, 6, PB), 256>>>(
        p_comb, p_sout, out + PD, PN, PD, PES, PESP, PD, PD,
        (long long)PN * PESP, (long long)PES * PD, (long long)129 * PD,
        nullptr, nullptr, nullptr, 0, 9999);
    // 12. cls1 (256,3072,K=768) — hybrid: y>=15 tensor (9 of 24 tiles)
    fgemm2<false, false, EP_BIAS_GELU><<<dim3(2, 24, 1), 256>>>(
        x, cw1, p_clsh, PB, 4 * PD, PD, 129 * PD, 4 * PD, 4 * PD,
        0, 0, 0, cb1, nullptr, nullptr, 0, 15);
    // 13. cls2 (256,768,K=3072) -> out row 0
    fgemm2<false, false, EP_BIAS><<<dim3(2, 6, 1), 256>>>(
        p_clsh, cw2, out, PB, PD, 4 * PD, 4 * PD, PD, 129 * PD,
        0, 0, 0, cb2, nullptr, nullptr, 0, 9999);
}

// round 11
// speedup vs baseline: 1.0241x; 1.0241x over previous
#include <cuda_runtime.h>
#include <cuda_bf16.h>
#include <math.h>
#include <cstdint>

// ---------------- problem constants ----------------
#define PB 256
#define PN 128
#define PD 768
#define PE 3
#define PS 44
#define PES 132
#define PESP 136          // padded combine ld
#define PMUP 144          // padded mu_cat ld
#define PH 1024
#define PMAXS 88
#define PM_TOK (PB*PN)
#define PM_FFN (PB*PS)

// ---------------- scratch (device globals) ----------------
__device__ float g_slot_input[PB * 769];
__device__ float g_slot_bias [PB * PD];
__device__ float g_img_n     [PM_TOK * PD];
__device__ float g_dot       [PM_TOK];
__device__ float g_mu_cat    [PD * PMUP];
__device__ float g_logits    [PM_TOK * PES];
__device__ float g_dispT     [PB * PES * PN];     // (b, 132, 128)
__device__ float g_combine   [PM_TOK * PESP];     // padded ld 136
__device__ float g_slot_in   [PB * PES * PD];
__device__ float g_hbuf      [PB * PES * PH];
__device__ float g_slot_out  [PB * PES * PD];
__device__ float g_cls_h     [PB * 4 * PD];

// ---------------- helpers ----------------
__device__ __forceinline__ float gelu_exact(float x) {
    return 0.5f * x * (1.0f + erff(x * 0.70710678118654752440f));
}
__device__ __forceinline__ void ffma2(unsigned long long& c,
                                      unsigned long long a,
                                      unsigned long long b) {
    asm("fma.rn.f32x2 %0, %1, %2, %0;" : "+l"(c) : "l"(a), "l"(b));
}
__device__ __forceinline__ uint32_t smem_u32(const void* p) {
    uint32_t a;
    asm("{ .reg .u64 t; cvta.to.shared.u64 t, %1; cvt.u32.u64 %0, t; }" : "=r"(a) : "l"(p));
    return a;
}
__device__ __forceinline__ void cp_async16(uint32_t dst, const void* src) {
    asm volatile("cp.async.cg.shared.global [%0], [%1], 16;" :: "r"(dst), "l"(src));
}
#define CP_COMMIT() asm volatile("cp.async.commit_group;" ::: "memory")
#define CP_WAIT0()  asm volatile("cp.async.wait_group 0;" ::: "memory")

// ---------------- FFMA2 tiled SGEMM: double-buffered, dup-A smem, B pipelined ----
// C[M,N] = A[M,K] @ B[K,N] row-major; batch via blockIdx.z strides.
// MAP_ROWS: row m -> (m/44)*132 + z*44 + m%44 on A & C (expert slicing).
#define EP_STORE     0
#define EP_BIAS      1
#define EP_BIAS_GELU 2
#define EP_LOGITS    3

// tile: BM=128, BN=128, BK=16; 256 threads; thread tile 8x8.
template<bool GUARD, bool MAP_ROWS, int EP>
__global__ __launch_bounds__(256)
void fgemm2(const float* __restrict__ A, const float* __restrict__ B,
            float* __restrict__ C,
            int M, int N, int K, int lda, int ldb, int ldc,
            long long sA, long long sB, long long sC,
            const float* __restrict__ v1, const float* __restrict__ v2,
            const float* __restrict__ scale_ptr, int biasStride)
{
    const int z = blockIdx.z;
    const float* Ab = A + (long long)z * sA;
    const float* Bb = B + (long long)z * sB;
    float*       Cb = C + (long long)z * sC;

    __shared__ __align__(16) float2 As[2][16][128];   // duplicated {v,v}, 32KB
    __shared__ __align__(16) float  Bs[2][16][128];   // 16KB

    const int tid = threadIdx.x;          // 256
    const int tx = tid & 15;
    const int ty = tid >> 4;
    const int m0 = blockIdx.x * 128;
    const int n0 = blockIdx.y * 128;

    unsigned long long acc[8][4];
    #pragma unroll
    for (int i = 0; i < 8; i++)
        #pragma unroll
        for (int p = 0; p < 4; p++) acc[i][p] = 0ull;

    // A loader: row tid>>1, k-half (tid&1)*8. B loader: k tid>>4, cols (tid&15)*8.
    const int a_r  = tid >> 1;
    const int a_c8 = (tid & 1) * 8;
    const int t_k = tid >> 4;
    const int t_c = (tid & 15) * 8;

    long long a_off = 0;
    bool a_ok = true;
    {
        const int gm = m0 + a_r;
        a_ok = !GUARD || (gm < M);
        int rr = gm;
        if (MAP_ROWS) rr = (gm / 44) * PES + z * PS + (gm % 44);
        a_off = (long long)rr * lda;
    }
    const bool aAlign = ((a_off & 3) == 0);
    const bool bColsOk = !GUARD || (n0 + 128 <= N);

    // cp.async destinations for B (fast path)
    const uint32_t bsu0 = smem_u32(&Bs[0][t_k][t_c]);
    const uint32_t bsu1 = smem_u32(&Bs[1][t_k][t_c]);

    const int nk = (K + 15) >> 4;
    float va[8], vb[8];

    auto load_a = [&](int kt) {
        const int k0 = kt << 4;
        const bool kfull = !GUARD || (k0 + 16 <= K);
        if ((!GUARD) || (a_ok && aAlign && kfull)) {
            const float4 u0 = *reinterpret_cast<const float4*>(Ab + a_off + k0 + a_c8);
            const float4 u1 = *reinterpret_cast<const float4*>(Ab + a_off + k0 + a_c8 + 4);
            va[0]=u0.x; va[1]=u0.y; va[2]=u0.z; va[3]=u0.w;
            va[4]=u1.x; va[5]=u1.y; va[6]=u1.z; va[7]=u1.w;
        } else {
            #pragma unroll
            for (int j = 0; j < 8; j++) {
                const int k = k0 + a_c8 + j;
                va[j] = (a_ok && k < K) ? Ab[a_off + k] : 0.f;
            }
        }
    };
    auto store_a = [&](int buf) {
        #pragma unroll
        for (int j = 0; j < 8; j++)
            As[buf][a_c8 + j][a_r] = make_float2(va[j], va[j]);
    };
    auto load_b_guard = [&](int kt) {
        const int k0 = kt << 4;
        const int gk = k0 + t_k;
        const long long ro = (long long)gk * ldb + n0 + t_c;
        if ((gk < K) && bColsOk && ((ro & 3) == 0)) {
            const float4 u0 = *reinterpret_cast<const float4*>(Bb + ro);
            const float4 u1 = *reinterpret_cast<const float4*>(Bb + ro + 4);
            vb[0]=u0.x; vb[1]=u0.y; vb[2]=u0.z; vb[3]=u0.w;
            vb[4]=u1.x; vb[5]=u1.y; vb[6]=u1.z; vb[7]=u1.w;
        } else {
            #pragma unroll
            for (int j = 0; j < 8; j++) {
                const int gn = n0 + t_c + j;
                vb[j] = (gk < K && gn < N) ? Bb[(long long)gk * ldb + gn] : 0.f;
            }
        }
    };
    auto store_b_guard = [&](int buf) {
        *reinterpret_cast<float4*>(&Bs[buf][t_k][t_c])     = make_float4(vb[0], vb[1], vb[2], vb[3]);
        *reinterpret_cast<float4*>(&Bs[buf][t_k][t_c + 4]) = make_float4(vb[4], vb[5], vb[6], vb[7]);
    };
    auto cp_b = [&](int kt, int buf) {
        const int gk = (kt << 4) + t_k;
        const float* src = Bb + (long long)gk * ldb + n0 + t_c;
        const uint32_t d = buf ? bsu1 : bsu0;
        cp_async16(d, src);
        cp_async16(d + 16, src + 4);
    };

    // ---- prologue: tile 0 ----
    load_a(0);
    if (GUARD) {
        load_b_guard(0);
        store_a(0);
        store_b_guard(0);
    } else {
        cp_b(0, 0);
        CP_COMMIT();
        store_a(0);
        CP_WAIT0();
    }
    __syncthreads();

    for (int kt = 0; kt < nk; kt++) {
        const int cur = kt & 1;
        const bool more = (kt + 1 < nk);
        if (more) {
            if (!GUARD) { cp_b(kt + 1, cur ^ 1); CP_COMMIT(); }
            else load_b_guard(kt + 1);
            load_a(kt + 1);
        }
        // ---- compute from buf cur: B fragments pipelined, A chunks from dup smem ----
        ulonglong2 cbl = *reinterpret_cast<const ulonglong2*>(&Bs[cur][0][tx * 4]);
        ulonglong2 cbh = *reinterpret_cast<const ulonglong2*>(&Bs[cur][0][64 + tx * 4]);
        #pragma unroll
        for (int k = 0; k < 16; k++) {
            const int kn = (k + 1) & 15;
            const ulonglong2 nbl = *reinterpret_cast<const ulonglong2*>(&Bs[cur][kn][tx * 4]);
            const ulonglong2 nbh = *reinterpret_cast<const ulonglong2*>(&Bs[cur][kn][64 + tx * 4]);
            #pragma unroll
            for (int c = 0; c < 4; c++) {
                const ulonglong2 ap = *reinterpret_cast<const ulonglong2*>(&As[cur][k][ty * 8 + 2 * c]);
                ffma2(acc[2*c][0],   ap.x, cbl.x);
                ffma2(acc[2*c][1],   ap.x, cbl.y);
                ffma2(acc[2*c][2],   ap.x, cbh.x);
                ffma2(acc[2*c][3],   ap.x, cbh.y);
                ffma2(acc[2*c+1][0], ap.y, cbl.x);
                ffma2(acc[2*c+1][1], ap.y, cbl.y);
                ffma2(acc[2*c+1][2], ap.y, cbh.x);
                ffma2(acc[2*c+1][3], ap.y, cbh.y);
            }
            cbl = nbl; cbh = nbh;
        }
        if (more) {
            store_a(cur ^ 1);
            if (GUARD) store_b_guard(cur ^ 1);
            else CP_WAIT0();
            __syncthreads();
        }
    }

    // ---- epilogue ----
    #pragma unroll
    for (int i = 0; i < 8; i++) {
        const int gm = m0 + ty * 8 + i;
        if (GUARD && gm >= M) continue;
        int rr = gm;
        if (MAP_ROWS) rr = (gm / 44) * PES + z * PS + (gm % 44);
        float dd = 0.f, sc = 0.f; int sel = 0;
        if (EP == EP_LOGITS) {
            const float w = v1[gm];
            sel = (w > 0.7f) ? 0 : ((w >= 0.3f) ? 1 : 2);
            dd = v2[gm];
            sc = scale_ptr[0];
        }
        float* crow = Cb + (long long)rr * ldc;
        #pragma unroll
        for (int p = 0; p < 4; p++) {
            const int gn0 = n0 + ((p < 2) ? (tx * 4 + p * 2) : (64 + tx * 4 + (p - 2) * 2));
            const uint2 u = *reinterpret_cast<const uint2*>(&acc[i][p]);
            #pragma unroll
            for (int h = 0; h < 2; h++) {
                const int gn = gn0 + h;
                if (GUARD && gn >= N) continue;
                float v = __uint_as_float(h ? u.y : u.x);
                if (EP == EP_BIAS) {
                    v += v1[z * biasStride + gn];
                } else if (EP == EP_BIAS_GELU) {
                    v = gelu_exact(v + v1[z * biasStride + gn]);
                } else if (EP == EP_LOGITS) {
                    v = ((gn / PS) == sel) ? sc * (v + dd) : 0.f;
                }
                crow[gn] = v;
            }
        }
    }
}

// ---------------- mu rearrange (padded ld 144) ----------------
__global__ void k_prep_mu(const float* __restrict__ mu, float* __restrict__ mu_cat) {
    int idx = blockIdx.x * blockDim.x + threadIdx.x;
    if (idx >= PD * PES) return;
    int d = idx / PES, j = idx % PES;
    int e = j / PS, s = j % PS;
    mu_cat[d * PMUP + j] = mu[((long long)e * PD + d) * PMAXS + s];
}

// ---------------- slot_input = [cls, mean(attn)] ----------------
__global__ void k_build_slotinput(const float* __restrict__ x,
                                  const float* __restrict__ attn,
                                  float* __restrict__ si) {
    int b = blockIdx.x;
    int t = threadIdx.x;
    __shared__ float red[8];
    float s = (t < PN) ? attn[b * PN + t] : 0.f;
    for (int o = 16; o; o >>= 1) s += __shfl_xor_sync(~0u, s, o);
    if ((t & 31) == 0) red[t >> 5] = s;
    __syncthreads();
    const float* cls = x + (long long)b * 129 * PD;
    float* o = si + (long long)b * 769;
    for (int d = t; d < PD; d += 256) o[d] = cls[d];
    if (t == 0) {
        float m = 0.f;
        #pragma unroll
        for (int i = 0; i < 8; i++) m += red[i];
        o[PD] = m * (1.f / (float)PN);
    }
}

// ---------------- LayerNorm + dot ----------------
__global__ void k_ln_dot(const float* __restrict__ x,
                         const float* __restrict__ gamma,
                         const float* __restrict__ beta,
                         const float* __restrict__ slot_bias,
                         float* __restrict__ img_n,
                         float* __restrict__ dot) {
    const int m = blockIdx.x;
    const int b = m >> 7;
    const int n = m & 127;
    const float* row = x + ((long long)b * 129 + 1 + n) * PD;
    const int t = threadIdx.x;
    const int w = t >> 5, l = t & 31;
    __shared__ float rs[8], rq[8];

    float v[3], s = 0.f, sq = 0.f;
    #pragma unroll
    for (int i = 0; i < 3; i++) {
        v[i] = row[t + i * 256];
        s += v[i];
        sq += v[i] * v[i];
    }
    for (int o = 16; o; o >>= 1) {
        s  += __shfl_xor_sync(~0u, s, o);
        sq += __shfl_xor_sync(~0u, sq, o);
    }
    if (l == 0) { rs[w] = s; rq[w] = sq; }
    __syncthreads();
    float ts = 0.f, tq = 0.f;
    #pragma unroll
    for (int i = 0; i < 8; i++) { ts += rs[i]; tq += rq[i]; }
    const float mean = ts * (1.f / (float)PD);
    const float var  = tq * (1.f / (float)PD) - mean * mean;
    const float inv  = rsqrtf(var + 1e-5f);
    __syncthreads();

    const float* sb = slot_bias + (long long)b * PD;
    float* orow = img_n + (long long)m * PD;
    float dp = 0.f;
    #pragma unroll
    for (int i = 0; i < 3; i++) {
        const int d = t + i * 256;
        const float y = (v[i] - mean) * inv * gamma[d] + beta[d];
        orow[d] = y;
        dp += y * sb[d];
    }
    for (int o = 16; o; o >>= 1) dp += __shfl_xor_sync(~0u, dp, o);
    if (l == 0) rs[w] = dp;
    __syncthreads();
    if (t == 0) {
        float d2 = 0.f;
        #pragma unroll
        for (int i = 0; i < 8; i++) d2 += rs[i];
        dot[m] = d2;
    }
}

// ---------------- dispatch softmax -> transposed output ----------------
__global__ void k_dispatch(const float* __restrict__ logits, float* __restrict__ dispT) {
    const int be = blockIdx.x;
    const int b = be / PE, e = be % PE;
    __shared__ float tile[PN][PS];
    __shared__ float csum[PS];
    const int t = threadIdx.x;
    const float* base = logits + (long long)b * PN * PES + e * PS;
    for (int idx = t; idx < PN * PS; idx += 256) {
        const int n = idx / PS, j = idx % PS;
        tile[n][j] = base[(long long)n * PES + j];
    }
    __syncthreads();
    if (t < PS) {
        float mx = -1e30f;
        for (int n = 0; n < PN; n++) mx = fmaxf(mx, tile[n][t]);
        float sm = 0.f;
        for (int n = 0; n < PN; n++) {
            const float ev = expf(tile[n][t] - mx);
            tile[n][t] = ev;
            sm += ev;
        }
        csum[t] = sm;
    }
    __syncthreads();
    float* ob = dispT + (long long)b * PES * PN + (long long)e * PS * PN;
    for (int idx = t; idx < PN * PS; idx += 256) {
        const int j = idx >> 7, n = idx & 127;
        ob[j * PN + n] = tile[n][j] / csum[j];
    }
}

// ---------------- combine softmax (padded ld out) ----------------
__global__ void k_combine(const float* __restrict__ logits, float* __restrict__ comb) {
    const int row = blockIdx.x * 8 + (threadIdx.x >> 5);
    const int l = threadIdx.x & 31;
    if (row >= PM_TOK) return;
    const float* r = logits + (long long)row * PES;
    float vals[5], mx = -1e30f;
    #pragma unroll
    for (int i = 0; i < 5; i++) {
        const int j = l + i * 32;
        vals[i] = (j < PES) ? r[j] : -1e30f;
        mx = fmaxf(mx, vals[i]);
    }
    for (int o = 16; o; o >>= 1) mx = fmaxf(mx, __shfl_xor_sync(~0u, mx, o));
    float s = 0.f;
    #pragma unroll
    for (int i = 0; i < 5; i++) {
        const int j = l + i * 32;
        if (j < PES) { vals[i] = expf(vals[i] - mx); s += vals[i]; }
    }
    for (int o = 16; o; o >>= 1) s += __shfl_xor_sync(~0u, s, o);
    const float inv = 1.f / s;
    float* o = comb + (long long)row * PESP;
    #pragma unroll
    for (int i = 0; i < 5; i++) {
        const int j = l + i * 32;
        if (j < PES) o[j] = vals[i] * inv;
    }
}

// ---------------- launch ----------------
extern "C" void kernel_launch(void* const* d_in, const int* in_sizes, int n_in,
                              void* d_out, int out_size) {
    const float* x      = (const float*)d_in[0];
    const float* attn   = (const float*)d_in[1];
    const float* gamma  = (const float*)d_in[2];
    const float* beta   = (const float*)d_in[3];
    const float* vsg_w  = (const float*)d_in[4];
    const float* vsg_b  = (const float*)d_in[5];
    const float* mu     = (const float*)d_in[6];
    const float* scale  = (const float*)d_in[7];
    const float* w1     = (const float*)d_in[8];
    const float* b1     = (const float*)d_in[9];
    const float* w2     = (const float*)d_in[10];
    const float* b2     = (const float*)d_in[11];
    const float* cw1    = (const float*)d_in[12];
    const float* cb1    = (const float*)d_in[13];
    const float* cw2    = (const float*)d_in[14];
    const float* cb2    = (const float*)d_in[15];
    float* out = (float*)d_out;

    float *p_si, *p_sb, *p_imgn, *p_dot, *p_mu, *p_log, *p_dispT, *p_comb;
    float *p_sin, *p_h, *p_sout, *p_clsh;
    cudaGetSymbolAddress((void**)&p_si,    g_slot_input);
    cudaGetSymbolAddress((void**)&p_sb,    g_slot_bias);
    cudaGetSymbolAddress((void**)&p_imgn,  g_img_n);
    cudaGetSymbolAddress((void**)&p_dot,   g_dot);
    cudaGetSymbolAddress((void**)&p_mu,    g_mu_cat);
    cudaGetSymbolAddress((void**)&p_log,   g_logits);
    cudaGetSymbolAddress((void**)&p_dispT, g_dispT);
    cudaGetSymbolAddress((void**)&p_comb,  g_combine);
    cudaGetSymbolAddress((void**)&p_sin,   g_slot_in);
    cudaGetSymbolAddress((void**)&p_h,     g_hbuf);
    cudaGetSymbolAddress((void**)&p_sout,  g_slot_out);
    cudaGetSymbolAddress((void**)&p_clsh,  g_cls_h);

    // 1. mu -> (768, 144-padded 132)
    k_prep_mu<<<(PD * PES + 255) / 256, 256>>>(mu, p_mu);
    // 2. slot_input
    k_build_slotinput<<<PB, 256>>>(x, attn, p_si);
    // 3. slot_bias = slot_input @ vsg_w + vsg_b   (256,768,K=769)
    fgemm2<true, false, EP_BIAS><<<dim3(2, 6, 1), 256>>>(
        p_si, vsg_w, p_sb, PB, PD, 769, 769, PD, PD,
        0, 0, 0, vsg_b, nullptr, nullptr, 0);
    // 4. LayerNorm + dot
    k_ln_dot<<<PM_TOK, 256>>>(x, gamma, beta, p_sb, p_imgn, p_dot);
    // 5. logits (32768,132,K=768)
    fgemm2<true, false, EP_LOGITS><<<dim3(PM_TOK / 128, 2, 1), 256>>>(
        p_imgn, p_mu, p_log, PM_TOK, PES, PD, PD, PMUP, PES,
        0, 0, 0, attn, p_dot, scale, 0);
    // 6/7. softmaxes
    k_dispatch<<<PB * PE, 256>>>(p_log, p_dispT);
    k_combine<<<PM_TOK / 8, 256>>>(p_log, p_comb);
    // 8. slot_in[b] = dispT[b] @ img[b]   (132,768,K=128) batched
    fgemm2<true, false, EP_STORE><<<dim3(2, 6, PB), 256>>>(
        p_dispT, x + PD, p_sin, PES, PD, PN, PN, PD, PD,
        (long long)PES * PN, (long long)129 * PD, (long long)PES * PD,
        nullptr, nullptr, nullptr, 0);
    // 9. FFN1 (11264,1024,K=768) per expert
    fgemm2<false, true, EP_BIAS_GELU><<<dim3(PM_FFN / 128, PH / 128, PE), 256>>>(
        p_sin, w1, p_h, PM_FFN, PH, PD, PD, PH, PH,
        0, (long long)PD * PH, 0, b1, nullptr, nullptr, PH);
    // 10. FFN2 (11264,768,K=1024) per expert
    fgemm2<false, true, EP_BIAS><<<dim3(PM_FFN / 128, PD / 128, PE), 256>>>(
        p_h, w2, p_sout, PM_FFN, PD, PH, PH, PD, PD,
        0, (long long)PH * PD, 0, b2, nullptr, nullptr, PD);
    // 11. img_out[b] = combine[b] @ slot_out[b]  (128,768,K=132) batched
    fgemm2<true, false, EP_STORE><<<dim3(1, 6, PB), 256>>>(
        p_comb, p_sout, out + PD, PN, PD, PES, PESP, PD, PD,
        (long long)PN * PESP, (long long)PES * PD, (long long)129 * PD,
        nullptr, nullptr, nullptr, 0);
    // 12. cls1 (256,3072,K=768)
    fgemm2<false, false, EP_BIAS_GELU><<<dim3(2, 24, 1), 256>>>(
        x, cw1, p_clsh, PB, 4 * PD, PD, 129 * PD, 4 * PD, 4 * PD,
        0, 0, 0, cb1, nullptr, nullptr, 0);
    // 13. cls2 (256,768,K=3072) -> out row 0
    fgemm2<false, false, EP_BIAS><<<dim3(2, 6, 1), 256>>>(
        p_clsh, cw2, out, PB, PD, 4 * PD, 4 * PD, PD, 129 * PD,
        0, 0, 0, cb2, nullptr, nullptr, 0);
}

// round 12
// speedup vs baseline: 1.2774x; 1.2472x over previous
#include <cuda_runtime.h>
#include <cuda_bf16.h>
#include <math.h>
#include <cstdint>

// ---------------- problem constants ----------------
#define PB 256
#define PN 128
#define PD 768
#define PE 3
#define PS 44
#define PES 132
#define PESP 136          // padded combine ld
#define PMUP 144          // padded mu_cat ld
#define PH 1024
#define PMAXS 88
#define PM_TOK (PB*PN)
#define PM_FFN (PB*PS)

// ---------------- scratch (device globals) ----------------
__device__ float g_slot_input[PB * 769];
__device__ float g_slot_bias [PB * PD];
__device__ float g_img_n     [PM_TOK * PD];
__device__ float g_dot       [PM_TOK];
__device__ float g_mu_cat    [PD * PMUP];
__device__ float g_logits    [PM_TOK * PES];
__device__ float g_dispT     [PB * PES * PN];     // (b, 132, 128)
__device__ float g_combine   [PM_TOK * PESP];     // padded ld 136
__device__ float g_slot_in   [PB * PES * PD];
__device__ float g_hbuf      [PB * PES * PH];
__device__ float g_slot_out  [PB * PES * PD];
__device__ float g_cls_h     [PB * 4 * PD];

// ---------------- helpers ----------------
__device__ __forceinline__ float gelu_exact(float x) {
    return 0.5f * x * (1.0f + erff(x * 0.70710678118654752440f));
}
__device__ __forceinline__ unsigned long long bcast2(float x) {
    unsigned long long r;
    asm("mov.b64 %0, {%1, %1};" : "=l"(r) : "r"(__float_as_uint(x)));
    return r;
}
__device__ __forceinline__ void ffma2(unsigned long long& c,
                                      unsigned long long a,
                                      unsigned long long b) {
    asm("fma.rn.f32x2 %0, %1, %2, %0;" : "+l"(c) : "l"(a), "l"(b));
}
__device__ __forceinline__ uint32_t smem_u32(const void* p) {
    uint32_t a;
    asm("{ .reg .u64 t; cvta.to.shared.u64 t, %1; cvt.u32.u64 %0, t; }" : "=r"(a) : "l"(p));
    return a;
}
__device__ __forceinline__ void cp_async16(uint32_t dst, const void* src) {
    asm volatile("cp.async.cg.shared.global [%0], [%1], 16;" :: "r"(dst), "l"(src));
}
#define CP_COMMIT() asm volatile("cp.async.commit_group;" ::: "memory")
#define CP_WAIT0()  asm volatile("cp.async.wait_group 0;" ::: "memory")

// ---------------- FFMA2 tiled SGEMM, double-buffered + pipelined (R9 exact) ----
// C[M,N] = A[M,K] @ B[K,N] row-major; batch via blockIdx.z strides.
// MAP_ROWS: row m -> (m/44)*132 + z*44 + m%44 on A & C (expert slicing).
#define EP_STORE     0
#define EP_BIAS      1
#define EP_BIAS_GELU 2
#define EP_LOGITS    3

// tile: BM=128, BN=128, BK=16; 256 threads; thread tile 8x8.
template<bool GUARD, bool MAP_ROWS, int EP>
__global__ __launch_bounds__(256)
void fgemm2(const float* __restrict__ A, const float* __restrict__ B,
            float* __restrict__ C,
            int M, int N, int K, int lda, int ldb, int ldc,
            long long sA, long long sB, long long sC,
            const float* __restrict__ v1, const float* __restrict__ v2,
            const float* __restrict__ scale_ptr, int biasStride)
{
    const int z = blockIdx.z;
    const float* Ab = A + (long long)z * sA;
    const float* Bb = B + (long long)z * sB;
    float*       Cb = C + (long long)z * sC;

    __shared__ __align__(16) float As[2][16][128];
    __shared__ __align__(16) float Bs[2][16][128];

    const int tid = threadIdx.x;          // 256
    const int tx = tid & 15;
    const int ty = tid >> 4;
    const int m0 = blockIdx.x * 128;
    const int n0 = blockIdx.y * 128;

    unsigned long long acc[8][4];
    #pragma unroll
    for (int i = 0; i < 8; i++)
        #pragma unroll
        for (int p = 0; p < 4; p++) acc[i][p] = 0ull;

    // A loader: row tid>>1, k-half (tid&1)*8. B loader: k tid>>4, cols (tid&15)*8.
    const int a_r  = tid >> 1;
    const int a_c8 = (tid & 1) * 8;
    const int t_k = tid >> 4;
    const int t_c = (tid & 15) * 8;

    long long a_off = 0;
    bool a_ok = true;
    {
        const int gm = m0 + a_r;
        a_ok = !GUARD || (gm < M);
        int rr = gm;
        if (MAP_ROWS) rr = (gm / 44) * PES + z * PS + (gm % 44);
        a_off = (long long)rr * lda;
    }
    const bool aAlign = ((a_off & 3) == 0);
    const bool bColsOk = !GUARD || (n0 + 128 <= N);

    // cp.async destinations for B (fast path)
    const uint32_t bsu0 = smem_u32(&Bs[0][t_k][t_c]);
    const uint32_t bsu1 = smem_u32(&Bs[1][t_k][t_c]);

    const int nk = (K + 15) >> 4;
    float va[8], vb[8];

    auto load_a = [&](int kt) {
        const int k0 = kt << 4;
        const bool kfull = !GUARD || (k0 + 16 <= K);
        if ((!GUARD) || (a_ok && aAlign && kfull)) {
            const float4 u0 = *reinterpret_cast<const float4*>(Ab + a_off + k0 + a_c8);
            const float4 u1 = *reinterpret_cast<const float4*>(Ab + a_off + k0 + a_c8 + 4);
            va[0]=u0.x; va[1]=u0.y; va[2]=u0.z; va[3]=u0.w;
            va[4]=u1.x; va[5]=u1.y; va[6]=u1.z; va[7]=u1.w;
        } else {
            #pragma unroll
            for (int j = 0; j < 8; j++) {
                const int k = k0 + a_c8 + j;
                va[j] = (a_ok && k < K) ? Ab[a_off + k] : 0.f;
            }
        }
    };
    auto store_a = [&](int buf) {
        #pragma unroll
        for (int j = 0; j < 8; j++) As[buf][a_c8 + j][a_r] = va[j];
    };
    auto load_b_guard = [&](int kt) {
        const int k0 = kt << 4;
        const int gk = k0 + t_k;
        const long long ro = (long long)gk * ldb + n0 + t_c;
        if ((gk < K) && bColsOk && ((ro & 3) == 0)) {
            const float4 u0 = *reinterpret_cast<const float4*>(Bb + ro);
            const float4 u1 = *reinterpret_cast<const float4*>(Bb + ro + 4);
            vb[0]=u0.x; vb[1]=u0.y; vb[2]=u0.z; vb[3]=u0.w;
            vb[4]=u1.x; vb[5]=u1.y; vb[6]=u1.z; vb[7]=u1.w;
        } else {
            #pragma unroll
            for (int j = 0; j < 8; j++) {
                const int gn = n0 + t_c + j;
                vb[j] = (gk < K && gn < N) ? Bb[(long long)gk * ldb + gn] : 0.f;
            }
        }
    };
    auto store_b_guard = [&](int buf) {
        *reinterpret_cast<float4*>(&Bs[buf][t_k][t_c])     = make_float4(vb[0], vb[1], vb[2], vb[3]);
        *reinterpret_cast<float4*>(&Bs[buf][t_k][t_c + 4]) = make_float4(vb[4], vb[5], vb[6], vb[7]);
    };
    auto cp_b = [&](int kt, int buf) {
        const int gk = (kt << 4) + t_k;
        const float* src = Bb + (long long)gk * ldb + n0 + t_c;
        const uint32_t d = buf ? bsu1 : bsu0;
        cp_async16(d, src);
        cp_async16(d + 16, src + 4);
    };

    // ---- prologue: tile 0 ----
    load_a(0);
    if (GUARD) {
        load_b_guard(0);
        store_a(0);
        store_b_guard(0);
    } else {
        cp_b(0, 0);
        CP_COMMIT();
        store_a(0);
        CP_WAIT0();
    }
    __syncthreads();

    for (int kt = 0; kt < nk; kt++) {
        const int cur = kt & 1;
        const bool more = (kt + 1 < nk);
        if (more) {
            if (!GUARD) { cp_b(kt + 1, cur ^ 1); CP_COMMIT(); }
            else load_b_guard(kt + 1);
            load_a(kt + 1);
        }
        // ---- compute from buf cur, register-pipelined fragments ----
        float4 ca0 = *reinterpret_cast<const float4*>(&As[cur][0][ty * 8]);
        float4 ca1 = *reinterpret_cast<const float4*>(&As[cur][0][ty * 8 + 4]);
        ulonglong2 cbl = *reinterpret_cast<const ulonglong2*>(&Bs[cur][0][tx * 4]);
        ulonglong2 cbh = *reinterpret_cast<const ulonglong2*>(&Bs[cur][0][64 + tx * 4]);
        #pragma unroll
        for (int k = 0; k < 16; k++) {
            const int kn = (k + 1) & 15;
            const float4 na0 = *reinterpret_cast<const float4*>(&As[cur][kn][ty * 8]);
            const float4 na1 = *reinterpret_cast<const float4*>(&As[cur][kn][ty * 8 + 4]);
            const ulonglong2 nbl = *reinterpret_cast<const ulonglong2*>(&Bs[cur][kn][tx * 4]);
            const ulonglong2 nbh = *reinterpret_cast<const ulonglong2*>(&Bs[cur][kn][64 + tx * 4]);
            const float av[8] = {ca0.x, ca0.y, ca0.z, ca0.w, ca1.x, ca1.y, ca1.z, ca1.w};
            #pragma unroll
            for (int i = 0; i < 8; i++) {
                const unsigned long long ap = bcast2(av[i]);
                ffma2(acc[i][0], ap, cbl.x);
                ffma2(acc[i][1], ap, cbl.y);
                ffma2(acc[i][2], ap, cbh.x);
                ffma2(acc[i][3], ap, cbh.y);
            }
            ca0 = na0; ca1 = na1; cbl = nbl; cbh = nbh;
        }
        if (more) {
            store_a(cur ^ 1);
            if (GUARD) store_b_guard(cur ^ 1);
            else CP_WAIT0();
            __syncthreads();
        }
    }

    // ---- epilogue ----
    #pragma unroll
    for (int i = 0; i < 8; i++) {
        const int gm = m0 + ty * 8 + i;
        if (GUARD && gm >= M) continue;
        int rr = gm;
        if (MAP_ROWS) rr = (gm / 44) * PES + z * PS + (gm % 44);
        float dd = 0.f, sc = 0.f; int sel = 0;
        if (EP == EP_LOGITS) {
            const float w = v1[gm];
            sel = (w > 0.7f) ? 0 : ((w >= 0.3f) ? 1 : 2);
            dd = v2[gm];
            sc = scale_ptr[0];
        }
        float* crow = Cb + (long long)rr * ldc;
        #pragma unroll
        for (int p = 0; p < 4; p++) {
            const int gn0 = n0 + ((p < 2) ? (tx * 4 + p * 2) : (64 + tx * 4 + (p - 2) * 2));
            const uint2 u = *reinterpret_cast<const uint2*>(&acc[i][p]);
            #pragma unroll
            for (int h = 0; h < 2; h++) {
                const int gn = gn0 + h;
                if (GUARD && gn >= N) continue;
                float v = __uint_as_float(h ? u.y : u.x);
                if (EP == EP_BIAS) {
                    v += v1[z * biasStride + gn];
                } else if (EP == EP_BIAS_GELU) {
                    v = gelu_exact(v + v1[z * biasStride + gn]);
                } else if (EP == EP_LOGITS) {
                    v = ((gn / PS) == sel) ? sc * (v + dd) : 0.f;
                }
                crow[gn] = v;
            }
        }
    }
}

// ---------------- logits tail: cols 128..131 (expert 2, slots 40..43) ----------------
// Rows with expert != 2 are exact zeros (mask); others: scale*(dot + row_dot).
__global__ void k_logits_tail(const float* __restrict__ img_n,
                              const float* __restrict__ mu_cat,
                              const float* __restrict__ attn,
                              const float* __restrict__ dot,
                              const float* __restrict__ scale_ptr,
                              float* __restrict__ logits)
{
    const int row = blockIdx.x * 8 + (threadIdx.x >> 5);
    const int l = threadIdx.x & 31;
    float* orow = logits + (long long)row * PES + 128;
    const float w = attn[row];
    if (!(w < 0.3f)) {            // expert sel != 2 -> masked to exact 0
        if (l < 4) orow[l] = 0.f;
        return;
    }
    const float* a = img_n + (long long)row * PD;
    float a0 = 0.f, a1 = 0.f, a2 = 0.f, a3 = 0.f;
    for (int k = l; k < PD; k += 32) {
        const float av = a[k];
        const float* mrow = mu_cat + k * PMUP + 128;
        a0 += av * mrow[0];
        a1 += av * mrow[1];
        a2 += av * mrow[2];
        a3 += av * mrow[3];
    }
    for (int o = 16; o; o >>= 1) {
        a0 += __shfl_xor_sync(~0u, a0, o);
        a1 += __shfl_xor_sync(~0u, a1, o);
        a2 += __shfl_xor_sync(~0u, a2, o);
        a3 += __shfl_xor_sync(~0u, a3, o);
    }
    if (l == 0) {
        const float sc = scale_ptr[0];
        const float dd = dot[row];
        orow[0] = sc * (a0 + dd);
        orow[1] = sc * (a1 + dd);
        orow[2] = sc * (a2 + dd);
        orow[3] = sc * (a3 + dd);
    }
}

// ---------------- slot_in tail: rows 128..131 per batch ----------------
// slot_in[b][j][d] = sum_n dispT[b][j][n] * img[b][n][d], j in 128..131.
__global__ void k_slotin_tail(const float* __restrict__ dispT,
                              const float* __restrict__ x,
                              float* __restrict__ slot_in)
{
    const int b = blockIdx.x;
    const int t = threadIdx.x;   // 256
    const float* img = x + (long long)b * 129 * PD + PD;
    const float* wrow = dispT + (long long)b * PES * PN + 128 * PN;
    __shared__ float wsh[4][PN];
    for (int i = t; i < 4 * PN; i += 256) wsh[i >> 7][i & 127] = wrow[i];
    __syncthreads();
    for (int d = t; d < PD; d += 256) {
        float a0 = 0.f, a1 = 0.f, a2 = 0.f, a3 = 0.f;
        #pragma unroll 4
        for (int n = 0; n < PN; n++) {
            const float v = img[(long long)n * PD + d];
            a0 += wsh[0][n] * v;
            a1 += wsh[1][n] * v;
            a2 += wsh[2][n] * v;
            a3 += wsh[3][n] * v;
        }
        float* o = slot_in + (long long)b * PES * PD + (long long)128 * PD + d;
        o[0]      = a0;
        o[PD]     = a1;
        o[2 * PD] = a2;
        o[3 * PD] = a3;
    }
}

// ---------------- mu rearrange (padded ld 144) ----------------
__global__ void k_prep_mu(const float* __restrict__ mu, float* __restrict__ mu_cat) {
    int idx = blockIdx.x * blockDim.x + threadIdx.x;
    if (idx >= PD * PES) return;
    int d = idx / PES, j = idx % PES;
    int e = j / PS, s = j % PS;
    mu_cat[d * PMUP + j] = mu[((long long)e * PD + d) * PMAXS + s];
}

// ---------------- slot_input = [cls, mean(attn)] ----------------
__global__ void k_build_slotinput(const float* __restrict__ x,
                                  const float* __restrict__ attn,
                                  float* __restrict__ si) {
    int b = blockIdx.x;
    int t = threadIdx.x;
    __shared__ float red[8];
    float s = (t < PN) ? attn[b * PN + t] : 0.f;
    for (int o = 16; o; o >>= 1) s += __shfl_xor_sync(~0u, s, o);
    if ((t & 31) == 0) red[t >> 5] = s;
    __syncthreads();
    const float* cls = x + (long long)b * 129 * PD;
    float* o = si + (long long)b * 769;
    for (int d = t; d < PD; d += 256) o[d] = cls[d];
    if (t == 0) {
        float m = 0.f;
        #pragma unroll
        for (int i = 0; i < 8; i++) m += red[i];
        o[PD] = m * (1.f / (float)PN);
    }
}

// ---------------- LayerNorm + dot ----------------
__global__ void k_ln_dot(const float* __restrict__ x,
                         const float* __restrict__ gamma,
                         const float* __restrict__ beta,
                         const float* __restrict__ slot_bias,
                         float* __restrict__ img_n,
                         float* __restrict__ dot) {
    const int m = blockIdx.x;
    const int b = m >> 7;
    const int n = m & 127;
    const float* row = x + ((long long)b * 129 + 1 + n) * PD;
    const int t = threadIdx.x;
    const int w = t >> 5, l = t & 31;
    __shared__ float rs[8], rq[8];

    float v[3], s = 0.f, sq = 0.f;
    #pragma unroll
    for (int i = 0; i < 3; i++) {
        v[i] = row[t + i * 256];
        s += v[i];
        sq += v[i] * v[i];
    }
    for (int o = 16; o; o >>= 1) {
        s  += __shfl_xor_sync(~0u, s, o);
        sq += __shfl_xor_sync(~0u, sq, o);
    }
    if (l == 0) { rs[w] = s; rq[w] = sq; }
    __syncthreads();
    float ts = 0.f, tq = 0.f;
    #pragma unroll
    for (int i = 0; i < 8; i++) { ts += rs[i]; tq += rq[i]; }
    const float mean = ts * (1.f / (float)PD);
    const float var  = tq * (1.f / (float)PD) - mean * mean;
    const float inv  = rsqrtf(var + 1e-5f);
    __syncthreads();

    const float* sb = slot_bias + (long long)b * PD;
    float* orow = img_n + (long long)m * PD;
    float dp = 0.f;
    #pragma unroll
    for (int i = 0; i < 3; i++) {
        const int d = t + i * 256;
        const float y = (v[i] - mean) * inv * gamma[d] + beta[d];
        orow[d] = y;
        dp += y * sb[d];
    }
    for (int o = 16; o; o >>= 1) dp += __shfl_xor_sync(~0u, dp, o);
    if (l == 0) rs[w] = dp;
    __syncthreads();
    if (t == 0) {
        float d2 = 0.f;
        #pragma unroll
        for (int i = 0; i < 8; i++) d2 += rs[i];
        dot[m] = d2;
    }
}

// ---------------- dispatch softmax -> transposed output ----------------
__global__ void k_dispatch(const float* __restrict__ logits, float* __restrict__ dispT) {
    const int be = blockIdx.x;
    const int b = be / PE, e = be % PE;
    __shared__ float tile[PN][PS];
    __shared__ float csum[PS];
    const int t = threadIdx.x;
    const float* base = logits + (long long)b * PN * PES + e * PS;
    for (int idx = t; idx < PN * PS; idx += 256) {
        const int n = idx / PS, j = idx % PS;
        tile[n][j] = base[(long long)n * PES + j];
    }
    __syncthreads();
    if (t < PS) {
        float mx = -1e30f;
        for (int n = 0; n < PN; n++) mx = fmaxf(mx, tile[n][t]);
        float sm = 0.f;
        for (int n = 0; n < PN; n++) {
            const float ev = expf(tile[n][t] - mx);
            tile[n][t] = ev;
            sm += ev;
        }
        csum[t] = sm;
    }
    __syncthreads();
    float* ob = dispT + (long long)b * PES * PN + (long long)e * PS * PN;
    for (int idx = t; idx < PN * PS; idx += 256) {
        const int j = idx >> 7, n = idx & 127;
        ob[j * PN + n] = tile[n][j] / csum[j];
    }
}

// ---------------- combine softmax (padded ld out) ----------------
__global__ void k_combine(const float* __restrict__ logits, float* __restrict__ comb) {
    const int row = blockIdx.x * 8 + (threadIdx.x >> 5);
    const int l = threadIdx.x & 31;
    if (row >= PM_TOK) return;
    const float* r = logits + (long long)row * PES;
    float vals[5], mx = -1e30f;
    #pragma unroll
    for (int i = 0; i < 5; i++) {
        const int j = l + i * 32;
        vals[i] = (j < PES) ? r[j] : -1e30f;
        mx = fmaxf(mx, vals[i]);
    }
    for (int o = 16; o; o >>= 1) mx = fmaxf(mx, __shfl_xor_sync(~0u, mx, o));
    float s = 0.f;
    #pragma unroll
    for (int i = 0; i < 5; i++) {
        const int j = l + i * 32;
        if (j < PES) { vals[i] = expf(vals[i] - mx); s += vals[i]; }
    }
    for (int o = 16; o; o >>= 1) s += __shfl_xor_sync(~0u, s, o);
    const float inv = 1.f / s;
    float* o = comb + (long long)row * PESP;
    #pragma unroll
    for (int i = 0; i < 5; i++) {
        const int j = l + i * 32;
        if (j < PES) o[j] = vals[i] * inv;
    }
}

// ---------------- launch ----------------
extern "C" void kernel_launch(void* const* d_in, const int* in_sizes, int n_in,
                              void* d_out, int out_size) {
    const float* x      = (const float*)d_in[0];
    const float* attn   = (const float*)d_in[1];
    const float* gamma  = (const float*)d_in[2];
    const float* beta   = (const float*)d_in[3];
    const float* vsg_w  = (const float*)d_in[4];
    const float* vsg_b  = (const float*)d_in[5];
    const float* mu     = (const float*)d_in[6];
    const float* scale  = (const float*)d_in[7];
    const float* w1     = (const float*)d_in[8];
    const float* b1     = (const float*)d_in[9];
    const float* w2     = (const float*)d_in[10];
    const float* b2     = (const float*)d_in[11];
    const float* cw1    = (const float*)d_in[12];
    const float* cb1    = (const float*)d_in[13];
    const float* cw2    = (const float*)d_in[14];
    const float* cb2    = (const float*)d_in[15];
    float* out = (float*)d_out;

    float *p_si, *p_sb, *p_imgn, *p_dot, *p_mu, *p_log, *p_dispT, *p_comb;
    float *p_sin, *p_h, *p_sout, *p_clsh;
    cudaGetSymbolAddress((void**)&p_si,    g_slot_input);
    cudaGetSymbolAddress((void**)&p_sb,    g_slot_bias);
    cudaGetSymbolAddress((void**)&p_imgn,  g_img_n);
    cudaGetSymbolAddress((void**)&p_dot,   g_dot);
    cudaGetSymbolAddress((void**)&p_mu,    g_mu_cat);
    cudaGetSymbolAddress((void**)&p_log,   g_logits);
    cudaGetSymbolAddress((void**)&p_dispT, g_dispT);
    cudaGetSymbolAddress((void**)&p_comb,  g_combine);
    cudaGetSymbolAddress((void**)&p_sin,   g_slot_in);
    cudaGetSymbolAddress((void**)&p_h,     g_hbuf);
    cudaGetSymbolAddress((void**)&p_sout,  g_slot_out);
    cudaGetSymbolAddress((void**)&p_clsh,  g_cls_h);

    // 1. mu -> (768, 144-padded 132)
    k_prep_mu<<<(PD * PES + 255) / 256, 256>>>(mu, p_mu);
    // 2. slot_input
    k_build_slotinput<<<PB, 256>>>(x, attn, p_si);
    // 3. slot_bias = slot_input @ vsg_w + vsg_b   (256,768,K=769)
    fgemm2<true, false, EP_BIAS><<<dim3(2, 6, 1), 256>>>(
        p_si, vsg_w, p_sb, PB, PD, 769, 769, PD, PD,
        0, 0, 0, vsg_b, nullptr, nullptr, 0);
    // 4. LayerNorm + dot
    k_ln_dot<<<PM_TOK, 256>>>(x, gamma, beta, p_sb, p_imgn, p_dot);
    // 5. logits cols 0..127 (32768,128,K=768), cols 128..131 via tail kernel
    fgemm2<true, false, EP_LOGITS><<<dim3(PM_TOK / 128, 1, 1), 256>>>(
        p_imgn, p_mu, p_log, PM_TOK, PES, PD, PD, PMUP, PES,
        0, 0, 0, attn, p_dot, scale, 0);
    k_logits_tail<<<PM_TOK / 8, 256>>>(p_imgn, p_mu, attn, p_dot, scale, p_log);
    // 6/7. softmaxes
    k_dispatch<<<PB * PE, 256>>>(p_log, p_dispT);
    k_combine<<<PM_TOK / 8, 256>>>(p_log, p_comb);
    // 8. slot_in rows 0..127 (128,768,K=128) batched; rows 128..131 via tail
    fgemm2<true, false, EP_STORE><<<dim3(1, 6, PB), 256>>>(
        p_dispT, x + PD, p_sin, PES, PD, PN, PN, PD, PD,
        (long long)PES * PN, (long long)129 * PD, (long long)PES * PD,
        nullptr, nullptr, nullptr, 0);
    k_slotin_tail<<<PB, 256>>>(p_dispT, x, p_sin);
    // 9. FFN1 (11264,1024,K=768) per expert
    fgemm2<false, true, EP_BIAS_GELU><<<dim3(PM_FFN / 128, PH / 128, PE), 256>>>(
        p_sin, w1, p_h, PM_FFN, PH, PD, PD, PH, PH,
        0, (long long)PD * PH, 0, b1, nullptr, nullptr, PH);
    // 10. FFN2 (11264,768,K=1024) per expert
    fgemm2<false, true, EP_BIAS><<<dim3(PM_FFN / 128, PD / 128, PE), 256>>>(
        p_h, w2, p_sout, PM_FFN, PD, PH, PH, PD, PD,
        0, (long long)PH * PD, 0, b2, nullptr, nullptr, PD);
    // 11. img_out[b] = combine[b] @ slot_out[b]  (128,768,K=132) batched
    fgemm2<true, false, EP_STORE><<<dim3(1, 6, PB), 256>>>(
        p_comb, p_sout, out + PD, PN, PD, PES, PESP, PD, PD,
        (long long)PN * PESP, (long long)PES * PD, (long long)129 * PD,
        nullptr, nullptr, nullptr, 0);
    // 12. cls1 (256,3072,K=768)
    fgemm2<false, false, EP_BIAS_GELU><<<dim3(2, 24, 1), 256>>>(
        x, cw1, p_clsh, PB, 4 * PD, PD, 129 * PD, 4 * PD, 4 * PD,
        0, 0, 0, cb1, nullptr, nullptr, 0);
    // 13. cls2 (256,768,K=3072) -> out row 0
    fgemm2<false, false, EP_BIAS><<<dim3(2, 6, 1), 256>>>(
        p_clsh, cw2, out, PB, PD, 4 * PD, 4 * PD, PD, 129 * PD,
        0, 0, 0, cb2, nullptr, nullptr, 0);
}

// round 13
// speedup vs baseline: 1.4691x; 1.1501x over previous
#include <cuda_runtime.h>
#include <cuda_bf16.h>
#include <math.h>
#include <cstdint>

// ---------------- problem constants ----------------
#define PB 256
#define PN 128
#define PD 768
#define PE 3
#define PS 44
#define PES 132
#define PESP 136          // padded combine ld
#define PMUP 144          // padded mu_cat ld
#define PH 1024
#define PMAXS 88
#define PM_TOK (PB*PN)
#define PM_FFN (PB*PS)

// ---------------- scratch (device globals) ----------------
__device__ float g_slot_input[PB * 769];
__device__ float g_slot_bias [PB * PD];
__device__ float g_img_n     [PM_TOK * PD];
__device__ float g_dot       [PM_TOK];
__device__ float g_mu_cat    [PD * PMUP];
__device__ float g_logits    [PM_TOK * PES];
__device__ float g_dispT     [PB * PES * PN];     // (b, 132, 128)
__device__ float g_combine   [PM_TOK * PESP];     // padded ld 136
__device__ float g_slot_in   [PB * PES * PD];
__device__ float g_hbuf      [PB * PES * PH];
__device__ float g_slot_out  [PB * PES * PD];
__device__ float g_cls_h     [PB * 4 * PD];
__device__ float g_part      [3 * PB * 4 * PD];   // split-K partials (max: cls1 3x256x3072)

// ---------------- helpers ----------------
__device__ __forceinline__ float gelu_exact(float x) {
    return 0.5f * x * (1.0f + erff(x * 0.70710678118654752440f));
}
__device__ __forceinline__ unsigned long long bcast2(float x) {
    unsigned long long r;
    asm("mov.b64 %0, {%1, %1};" : "=l"(r) : "r"(__float_as_uint(x)));
    return r;
}
__device__ __forceinline__ void ffma2(unsigned long long& c,
                                      unsigned long long a,
                                      unsigned long long b) {
    asm("fma.rn.f32x2 %0, %1, %2, %0;" : "+l"(c) : "l"(a), "l"(b));
}
__device__ __forceinline__ uint32_t smem_u32(const void* p) {
    uint32_t a;
    asm("{ .reg .u64 t; cvta.to.shared.u64 t, %1; cvt.u32.u64 %0, t; }" : "=r"(a) : "l"(p));
    return a;
}
__device__ __forceinline__ void cp_async16(uint32_t dst, const void* src) {
    asm volatile("cp.async.cg.shared.global [%0], [%1], 16;" :: "r"(dst), "l"(src));
}
#define CP_COMMIT() asm volatile("cp.async.commit_group;" ::: "memory")
#define CP_WAIT0()  asm volatile("cp.async.wait_group 0;" ::: "memory")

// ---------------- FFMA2 tiled SGEMM, double-buffered + pipelined ----------------
// C[M,N] = A[M,K] @ B[K,N] row-major; batch via blockIdx.z strides.
// MAP_ROWS: row m -> (m/44)*132 + z*44 + m%44 on A & C (expert slicing).
// kChunk > 0: split-K mode — blockIdx.z selects K range [z*kChunk, min(K, ...));
//             C partial written at z*sC (epilogue must be EP_STORE).
#define EP_STORE     0
#define EP_BIAS      1
#define EP_BIAS_GELU 2
#define EP_LOGITS    3

// tile: BM=128, BN=128, BK=16; 256 threads; thread tile 8x8.
template<bool GUARD, bool MAP_ROWS, int EP>
__global__ __launch_bounds__(256)
void fgemm2(const float* __restrict__ A, const float* __restrict__ B,
            float* __restrict__ C,
            int M, int N, int K, int lda, int ldb, int ldc,
            long long sA, long long sB, long long sC,
            const float* __restrict__ v1, const float* __restrict__ v2,
            const float* __restrict__ scale_ptr, int biasStride,
            int kChunk)
{
    const int z = blockIdx.z;
    const float* Ab = A + (long long)z * sA;
    const float* Bb = B + (long long)z * sB;
    float*       Cb = C + (long long)z * sC;

    int ks = 0, ke = K;
    if (kChunk > 0) {
        ks = z * kChunk;
        ke = (K < ks + kChunk) ? K : (ks + kChunk);
    }

    __shared__ __align__(16) float As[2][16][128];
    __shared__ __align__(16) float Bs[2][16][128];

    const int tid = threadIdx.x;          // 256
    const int tx = tid & 15;
    const int ty = tid >> 4;
    const int m0 = blockIdx.x * 128;
    const int n0 = blockIdx.y * 128;

    unsigned long long acc[8][4];
    #pragma unroll
    for (int i = 0; i < 8; i++)
        #pragma unroll
        for (int p = 0; p < 4; p++) acc[i][p] = 0ull;

    // A loader: row tid>>1, k-half (tid&1)*8. B loader: k tid>>4, cols (tid&15)*8.
    const int a_r  = tid >> 1;
    const int a_c8 = (tid & 1) * 8;
    const int t_k = tid >> 4;
    const int t_c = (tid & 15) * 8;

    long long a_off = 0;
    bool a_ok = true;
    {
        const int gm = m0 + a_r;
        a_ok = !GUARD || (gm < M);
        int rr = gm;
        if (MAP_ROWS) rr = (gm / 44) * PES + z * PS + (gm % 44);
        a_off = (long long)rr * lda;
    }
    const bool aAlign = ((a_off & 3) == 0);
    const bool bColsOk = !GUARD || (n0 + 128 <= N);

    // cp.async destinations for B (fast path)
    const uint32_t bsu0 = smem_u32(&Bs[0][t_k][t_c]);
    const uint32_t bsu1 = smem_u32(&Bs[1][t_k][t_c]);

    const int nk = (ke - ks + 15) >> 4;
    float va[8], vb[8];

    // k0 = absolute K base of the 16-wide tile
    auto load_a = [&](int k0) {
        const bool kfull = !GUARD || (k0 + 16 <= ke);
        if ((!GUARD) || (a_ok && aAlign && kfull)) {
            const float4 u0 = *reinterpret_cast<const float4*>(Ab + a_off + k0 + a_c8);
            const float4 u1 = *reinterpret_cast<const float4*>(Ab + a_off + k0 + a_c8 + 4);
            va[0]=u0.x; va[1]=u0.y; va[2]=u0.z; va[3]=u0.w;
            va[4]=u1.x; va[5]=u1.y; va[6]=u1.z; va[7]=u1.w;
        } else {
            #pragma unroll
            for (int j = 0; j < 8; j++) {
                const int k = k0 + a_c8 + j;
                va[j] = (a_ok && k < ke) ? Ab[a_off + k] : 0.f;
            }
        }
    };
    auto store_a = [&](int buf) {
        #pragma unroll
        for (int j = 0; j < 8; j++) As[buf][a_c8 + j][a_r] = va[j];
    };
    auto load_b_guard = [&](int k0) {
        const int gk = k0 + t_k;
        const long long ro = (long long)gk * ldb + n0 + t_c;
        if ((gk < ke) && bColsOk && ((ro & 3) == 0)) {
            const float4 u0 = *reinterpret_cast<const float4*>(Bb + ro);
            const float4 u1 = *reinterpret_cast<const float4*>(Bb + ro + 4);
            vb[0]=u0.x; vb[1]=u0.y; vb[2]=u0.z; vb[3]=u0.w;
            vb[4]=u1.x; vb[5]=u1.y; vb[6]=u1.z; vb[7]=u1.w;
        } else {
            #pragma unroll
            for (int j = 0; j < 8; j++) {
                const int gn = n0 + t_c + j;
                vb[j] = (gk < ke && gn < N) ? Bb[(long long)gk * ldb + gn] : 0.f;
            }
        }
    };
    auto store_b_guard = [&](int buf) {
        *reinterpret_cast<float4*>(&Bs[buf][t_k][t_c])     = make_float4(vb[0], vb[1], vb[2], vb[3]);
        *reinterpret_cast<float4*>(&Bs[buf][t_k][t_c + 4]) = make_float4(vb[4], vb[5], vb[6], vb[7]);
    };
    auto cp_b = [&](int k0, int buf) {
        const int gk = k0 + t_k;
        const float* src = Bb + (long long)gk * ldb + n0 + t_c;
        const uint32_t d = buf ? bsu1 : bsu0;
        cp_async16(d, src);
        cp_async16(d + 16, src + 4);
    };

    // ---- prologue: tile 0 ----
    load_a(ks);
    if (GUARD) {
        load_b_guard(ks);
        store_a(0);
        store_b_guard(0);
    } else {
        cp_b(ks, 0);
        CP_COMMIT();
        store_a(0);
        CP_WAIT0();
    }
    __syncthreads();

    for (int kt = 0; kt < nk; kt++) {
        const int cur = kt & 1;
        const bool more = (kt + 1 < nk);
        if (more) {
            const int k0n = ks + ((kt + 1) << 4);
            if (!GUARD) { cp_b(k0n, cur ^ 1); CP_COMMIT(); }
            else load_b_guard(k0n);
            load_a(k0n);
        }
        // ---- compute from buf cur, register-pipelined fragments ----
        float4 ca0 = *reinterpret_cast<const float4*>(&As[cur][0][ty * 8]);
        float4 ca1 = *reinterpret_cast<const float4*>(&As[cur][0][ty * 8 + 4]);
        ulonglong2 cbl = *reinterpret_cast<const ulonglong2*>(&Bs[cur][0][tx * 4]);
        ulonglong2 cbh = *reinterpret_cast<const ulonglong2*>(&Bs[cur][0][64 + tx * 4]);
        #pragma unroll
        for (int k = 0; k < 16; k++) {
            const int kn = (k + 1) & 15;
            const float4 na0 = *reinterpret_cast<const float4*>(&As[cur][kn][ty * 8]);
            const float4 na1 = *reinterpret_cast<const float4*>(&As[cur][kn][ty * 8 + 4]);
            const ulonglong2 nbl = *reinterpret_cast<const ulonglong2*>(&Bs[cur][kn][tx * 4]);
            const ulonglong2 nbh = *reinterpret_cast<const ulonglong2*>(&Bs[cur][kn][64 + tx * 4]);
            const float av[8] = {ca0.x, ca0.y, ca0.z, ca0.w, ca1.x, ca1.y, ca1.z, ca1.w};
            #pragma unroll
            for (int i = 0; i < 8; i++) {
                const unsigned long long ap = bcast2(av[i]);
                ffma2(acc[i][0], ap, cbl.x);
                ffma2(acc[i][1], ap, cbl.y);
                ffma2(acc[i][2], ap, cbh.x);
                ffma2(acc[i][3], ap, cbh.y);
            }
            ca0 = na0; ca1 = na1; cbl = nbl; cbh = nbh;
        }
        if (more) {
            store_a(cur ^ 1);
            if (GUARD) store_b_guard(cur ^ 1);
            else CP_WAIT0();
            __syncthreads();
        }
    }

    // ---- epilogue ----
    #pragma unroll
    for (int i = 0; i < 8; i++) {
        const int gm = m0 + ty * 8 + i;
        if (GUARD && gm >= M) continue;
        int rr = gm;
        if (MAP_ROWS) rr = (gm / 44) * PES + z * PS + (gm % 44);
        float dd = 0.f, sc = 0.f; int sel = 0;
        if (EP == EP_LOGITS) {
            const float w = v1[gm];
            sel = (w > 0.7f) ? 0 : ((w >= 0.3f) ? 1 : 2);
            dd = v2[gm];
            sc = scale_ptr[0];
        }
        float* crow = Cb + (long long)rr * ldc;
        #pragma unroll
        for (int p = 0; p < 4; p++) {
            const int gn0 = n0 + ((p < 2) ? (tx * 4 + p * 2) : (64 + tx * 4 + (p - 2) * 2));
            const uint2 u = *reinterpret_cast<const uint2*>(&acc[i][p]);
            #pragma unroll
            for (int h = 0; h < 2; h++) {
                const int gn = gn0 + h;
                if (GUARD && gn >= N) continue;
                float v = __uint_as_float(h ? u.y : u.x);
                if (EP == EP_BIAS) {
                    v += v1[z * biasStride + gn];
                } else if (EP == EP_BIAS_GELU) {
                    v = gelu_exact(v + v1[z * biasStride + gn]);
                } else if (EP == EP_LOGITS) {
                    v = ((gn / PS) == sel) ? sc * (v + dd) : 0.f;
                }
                crow[gn] = v;
            }
        }
    }
}

// ---------------- split-K reduce: out = sum_z part[z] (+bias) (+gelu) ----------------
template<int EP>
__global__ void k_reduceK(const float* __restrict__ part, float* __restrict__ out,
                          int total, int N, long long stride, int nz,
                          const float* __restrict__ bias, int ldcOut)
{
    const int i = blockIdx.x * 256 + threadIdx.x;
    if (i >= total) return;
    float s = 0.f;
    for (int zz = 0; zz < nz; zz++) s += part[(long long)zz * stride + i];
    const int col = i % N;
    if (EP == EP_BIAS)           s += bias[col];
    else if (EP == EP_BIAS_GELU) s = gelu_exact(s + bias[col]);
    out[(long long)(i / N) * ldcOut + col] = s;
}

// ---------------- logits tail: cols 128..131 (expert 2, slots 40..43) ----------------
__global__ void k_logits_tail(const float* __restrict__ img_n,
                              const float* __restrict__ mu_cat,
                              const float* __restrict__ attn,
                              const float* __restrict__ dot,
                              const float* __restrict__ scale_ptr,
                              float* __restrict__ logits)
{
    const int row = blockIdx.x * 8 + (threadIdx.x >> 5);
    const int l = threadIdx.x & 31;
    float* orow = logits + (long long)row * PES + 128;
    const float w = attn[row];
    if (!(w < 0.3f)) {            // expert sel != 2 -> masked to exact 0
        if (l < 4) orow[l] = 0.f;
        return;
    }
    const float* a = img_n + (long long)row * PD;
    float a0 = 0.f, a1 = 0.f, a2 = 0.f, a3 = 0.f;
    for (int k = l; k < PD; k += 32) {
        const float av = a[k];
        const float* mrow = mu_cat + k * PMUP + 128;
        a0 += av * mrow[0];
        a1 += av * mrow[1];
        a2 += av * mrow[2];
        a3 += av * mrow[3];
    }
    for (int o = 16; o; o >>= 1) {
        a0 += __shfl_xor_sync(~0u, a0, o);
        a1 += __shfl_xor_sync(~0u, a1, o);
        a2 += __shfl_xor_sync(~0u, a2, o);
        a3 += __shfl_xor_sync(~0u, a3, o);
    }
    if (l == 0) {
        const float sc = scale_ptr[0];
        const float dd = dot[row];
        orow[0] = sc * (a0 + dd);
        orow[1] = sc * (a1 + dd);
        orow[2] = sc * (a2 + dd);
        orow[3] = sc * (a3 + dd);
    }
}

// ---------------- slot_in tail: rows 128..131 per batch ----------------
__global__ void k_slotin_tail(const float* __restrict__ dispT,
                              const float* __restrict__ x,
                              float* __restrict__ slot_in)
{
    const int b = blockIdx.x;
    const int t = threadIdx.x;   // 256
    const float* img = x + (long long)b * 129 * PD + PD;
    const float* wrow = dispT + (long long)b * PES * PN + 128 * PN;
    __shared__ float wsh[4][PN];
    for (int i = t; i < 4 * PN; i += 256) wsh[i >> 7][i & 127] = wrow[i];
    __syncthreads();
    for (int d = t; d < PD; d += 256) {
        float a0 = 0.f, a1 = 0.f, a2 = 0.f, a3 = 0.f;
        #pragma unroll 4
        for (int n = 0; n < PN; n++) {
            const float v = img[(long long)n * PD + d];
            a0 += wsh[0][n] * v;
            a1 += wsh[1][n] * v;
            a2 += wsh[2][n] * v;
            a3 += wsh[3][n] * v;
        }
        float* o = slot_in + (long long)b * PES * PD + (long long)128 * PD + d;
        o[0]      = a0;
        o[PD]     = a1;
        o[2 * PD] = a2;
        o[3 * PD] = a3;
    }
}

// ---------------- mu rearrange (padded ld 144) ----------------
__global__ void k_prep_mu(const float* __restrict__ mu, float* __restrict__ mu_cat) {
    int idx = blockIdx.x * blockDim.x + threadIdx.x;
    if (idx >= PD * PES) return;
    int d = idx / PES, j = idx % PES;
    int e = j / PS, s = j % PS;
    mu_cat[d * PMUP + j] = mu[((long long)e * PD + d) * PMAXS + s];
}

// ---------------- slot_input = [cls, mean(attn)] ----------------
__global__ void k_build_slotinput(const float* __restrict__ x,
                                  const float* __restrict__ attn,
                                  float* __restrict__ si) {
    int b = blockIdx.x;
    int t = threadIdx.x;
    __shared__ float red[8];
    float s = (t < PN) ? attn[b * PN + t] : 0.f;
    for (int o = 16; o; o >>= 1) s += __shfl_xor_sync(~0u, s, o);
    if ((t & 31) == 0) red[t >> 5] = s;
    __syncthreads();
    const float* cls = x + (long long)b * 129 * PD;
    float* o = si + (long long)b * 769;
    for (int d = t; d < PD; d += 256) o[d] = cls[d];
    if (t == 0) {
        float m = 0.f;
        #pragma unroll
        for (int i = 0; i < 8; i++) m += red[i];
        o[PD] = m * (1.f / (float)PN);
    }
}

// ---------------- LayerNorm + dot ----------------
__global__ void k_ln_dot(const float* __restrict__ x,
                         const float* __restrict__ gamma,
                         const float* __restrict__ beta,
                         const float* __restrict__ slot_bias,
                         float* __restrict__ img_n,
                         float* __restrict__ dot) {
    const int m = blockIdx.x;
    const int b = m >> 7;
    const int n = m & 127;
    const float* row = x + ((long long)b * 129 + 1 + n) * PD;
    const int t = threadIdx.x;
    const int w = t >> 5, l = t & 31;
    __shared__ float rs[8], rq[8];

    float v[3], s = 0.f, sq = 0.f;
    #pragma unroll
    for (int i = 0; i < 3; i++) {
        v[i] = row[t + i * 256];
        s += v[i];
        sq += v[i] * v[i];
    }
    for (int o = 16; o; o >>= 1) {
        s  += __shfl_xor_sync(~0u, s, o);
        sq += __shfl_xor_sync(~0u, sq, o);
    }
    if (l == 0) { rs[w] = s; rq[w] = sq; }
    __syncthreads();
    float ts = 0.f, tq = 0.f;
    #pragma unroll
    for (int i = 0; i < 8; i++) { ts += rs[i]; tq += rq[i]; }
    const float mean = ts * (1.f / (float)PD);
    const float var  = tq * (1.f / (float)PD) - mean * mean;
    const float inv  = rsqrtf(var + 1e-5f);
    __syncthreads();

    const float* sb = slot_bias + (long long)b * PD;
    float* orow = img_n + (long long)m * PD;
    float dp = 0.f;
    #pragma unroll
    for (int i = 0; i < 3; i++) {
        const int d = t + i * 256;
        const float y = (v[i] - mean) * inv * gamma[d] + beta[d];
        orow[d] = y;
        dp += y * sb[d];
    }
    for (int o = 16; o; o >>= 1) dp += __shfl_xor_sync(~0u, dp, o);
    if (l == 0) rs[w] = dp;
    __syncthreads();
    if (t == 0) {
        float d2 = 0.f;
        #pragma unroll
        for (int i = 0; i < 8; i++) d2 += rs[i];
        dot[m] = d2;
    }
}

// ---------------- dispatch softmax -> transposed output ----------------
__global__ void k_dispatch(const float* __restrict__ logits, float* __restrict__ dispT) {
    const int be = blockIdx.x;
    const int b = be / PE, e = be % PE;
    __shared__ float tile[PN][PS];
    __shared__ float csum[PS];
    const int t = threadIdx.x;
    const float* base = logits + (long long)b * PN * PES + e * PS;
    for (int idx = t; idx < PN * PS; idx += 256) {
        const int n = idx / PS, j = idx % PS;
        tile[n][j] = base[(long long)n * PES + j];
    }
    __syncthreads();
    if (t < PS) {
        float mx = -1e30f;
        for (int n = 0; n < PN; n++) mx = fmaxf(mx, tile[n][t]);
        float sm = 0.f;
        for (int n = 0; n < PN; n++) {
            const float ev = expf(tile[n][t] - mx);
            tile[n][t] = ev;
            sm += ev;
        }
        csum[t] = sm;
    }
    __syncthreads();
    float* ob = dispT + (long long)b * PES * PN + (long long)e * PS * PN;
    for (int idx = t; idx < PN * PS; idx += 256) {
        const int j = idx >> 7, n = idx & 127;
        ob[j * PN + n] = tile[n][j] / csum[j];
    }
}

// ---------------- combine softmax (padded ld out) ----------------
__global__ void k_combine(const float* __restrict__ logits, float* __restrict__ comb) {
    const int row = blockIdx.x * 8 + (threadIdx.x >> 5);
    const int l = threadIdx.x & 31;
    if (row >= PM_TOK) return;
    const float* r = logits + (long long)row * PES;
    float vals[5], mx = -1e30f;
    #pragma unroll
    for (int i = 0; i < 5; i++) {
        const int j = l + i * 32;
        vals[i] = (j < PES) ? r[j] : -1e30f;
        mx = fmaxf(mx, vals[i]);
    }
    for (int o = 16; o; o >>= 1) mx = fmaxf(mx, __shfl_xor_sync(~0u, mx, o));
    float s = 0.f;
    #pragma unroll
    for (int i = 0; i < 5; i++) {
        const int j = l + i * 32;
        if (j < PES) { vals[i] = expf(vals[i] - mx); s += vals[i]; }
    }
    for (int o = 16; o; o >>= 1) s += __shfl_xor_sync(~0u, s, o);
    const float inv = 1.f / s;
    float* o = comb + (long long)row * PESP;
    #pragma unroll
    for (int i = 0; i < 5; i++) {
        const int j = l + i * 32;
        if (j < PES) o[j] = vals[i] * inv;
    }
}

// ---------------- launch ----------------
extern "C" void kernel_launch(void* const* d_in, const int* in_sizes, int n_in,
                              void* d_out, int out_size) {
    const float* x      = (const float*)d_in[0];
    const float* attn   = (const float*)d_in[1];
    const float* gamma  = (const float*)d_in[2];
    const float* beta   = (const float*)d_in[3];
    const float* vsg_w  = (const float*)d_in[4];
    const float* vsg_b  = (const float*)d_in[5];
    const float* mu     = (const float*)d_in[6];
    const float* scale  = (const float*)d_in[7];
    const float* w1     = (const float*)d_in[8];
    const float* b1     = (const float*)d_in[9];
    const float* w2     = (const float*)d_in[10];
    const float* b2     = (const float*)d_in[11];
    const float* cw1    = (const float*)d_in[12];
    const float* cb1    = (const float*)d_in[13];
    const float* cw2    = (const float*)d_in[14];
    const float* cb2    = (const float*)d_in[15];
    float* out = (float*)d_out;

    float *p_si, *p_sb, *p_imgn, *p_dot, *p_mu, *p_log, *p_dispT, *p_comb;
    float *p_sin, *p_h, *p_sout, *p_clsh, *p_part;
    cudaGetSymbolAddress((void**)&p_si,    g_slot_input);
    cudaGetSymbolAddress((void**)&p_sb,    g_slot_bias);
    cudaGetSymbolAddress((void**)&p_imgn,  g_img_n);
    cudaGetSymbolAddress((void**)&p_dot,   g_dot);
    cudaGetSymbolAddress((void**)&p_mu,    g_mu_cat);
    cudaGetSymbolAddress((void**)&p_log,   g_logits);
    cudaGetSymbolAddress((void**)&p_dispT, g_dispT);
    cudaGetSymbolAddress((void**)&p_comb,  g_combine);
    cudaGetSymbolAddress((void**)&p_sin,   g_slot_in);
    cudaGetSymbolAddress((void**)&p_h,     g_hbuf);
    cudaGetSymbolAddress((void**)&p_sout,  g_slot_out);
    cudaGetSymbolAddress((void**)&p_clsh,  g_cls_h);
    cudaGetSymbolAddress((void**)&p_part,  g_part);

    // 1. mu -> (768, 144-padded 132)
    k_prep_mu<<<(PD * PES + 255) / 256, 256>>>(mu, p_mu);
    // 2. slot_input
    k_build_slotinput<<<PB, 256>>>(x, attn, p_si);
    // 3. slot_bias: split-K 4 (chunks of 208; last 145) then reduce + bias
    fgemm2<true, false, EP_STORE><<<dim3(2, 6, 4), 256>>>(
        p_si, vsg_w, p_part, PB, PD, 769, 769, PD, PD,
        0, 0, (long long)PB * PD, nullptr, nullptr, nullptr, 0, 208);
    k_reduceK<EP_BIAS><<<(PB * PD + 255) / 256, 256>>>(
        p_part, p_sb, PB * PD, PD, (long long)PB * PD, 4, vsg_b, PD);
    // 4. LayerNorm + dot
    k_ln_dot<<<PM_TOK, 256>>>(x, gamma, beta, p_sb, p_imgn, p_dot);
    // 5. logits cols 0..127 (32768,128,K=768), cols 128..131 via tail kernel
    fgemm2<true, false, EP_LOGITS><<<dim3(PM_TOK / 128, 1, 1), 256>>>(
        p_imgn, p_mu, p_log, PM_TOK, PES, PD, PD, PMUP, PES,
        0, 0, 0, attn, p_dot, scale, 0, 0);
    k_logits_tail<<<PM_TOK / 8, 256>>>(p_imgn, p_mu, attn, p_dot, scale, p_log);
    // 6/7. softmaxes
    k_dispatch<<<PB * PE, 256>>>(p_log, p_dispT);
    k_combine<<<PM_TOK / 8, 256>>>(p_log, p_comb);
    // 8. slot_in rows 0..127 (128,768,K=128) batched; rows 128..131 via tail
    fgemm2<true, false, EP_STORE><<<dim3(1, 6, PB), 256>>>(
        p_dispT, x + PD, p_sin, PES, PD, PN, PN, PD, PD,
        (long long)PES * PN, (long long)129 * PD, (long long)PES * PD,
        nullptr, nullptr, nullptr, 0, 0);
    k_slotin_tail<<<PB, 256>>>(p_dispT, x, p_sin);
    // 9. FFN1 (11264,1024,K=768) per expert
    fgemm2<false, true, EP_BIAS_GELU><<<dim3(PM_FFN / 128, PH / 128, PE), 256>>>(
        p_sin, w1, p_h, PM_FFN, PH, PD, PD, PH, PH,
        0, (long long)PD * PH, 0, b1, nullptr, nullptr, PH, 0);
    // 10. FFN2 (11264,768,K=1024) per expert
    fgemm2<false, true, EP_BIAS><<<dim3(PM_FFN / 128, PD / 128, PE), 256>>>(
        p_h, w2, p_sout, PM_FFN, PD, PH, PH, PD, PD,
        0, (long long)PH * PD, 0, b2, nullptr, nullptr, PD, 0);
    // 11. img_out[b] = combine[b] @ slot_out[b]  (128,768,K=132) batched
    fgemm2<true, false, EP_STORE><<<dim3(1, 6, PB), 256>>>(
        p_comb, p_sout, out + PD, PN, PD, PES, PESP, PD, PD,
        (long long)PN * PESP, (long long)PES * PD, (long long)129 * PD,
        nullptr, nullptr, nullptr, 0, 0);
    // 12. cls1 (256,3072,K=768): split-K 3 (chunks 256) then reduce + bias + gelu
    fgemm2<false, false, EP_STORE><<<dim3(2, 24, 3), 256>>>(
        x, cw1, p_part, PB, 4 * PD, PD, 129 * PD, 4 * PD, 4 * PD,
        0, 0, (long long)PB * 4 * PD, nullptr, nullptr, nullptr, 0, 256);
    k_reduceK<EP_BIAS_GELU><<<(PB * 4 * PD + 255) / 256, 256>>>(
        p_part, p_clsh, PB * 4 * PD, 4 * PD, (long long)PB * 4 * PD, 3, cb1, 4 * PD);
    // 13. cls2 (256,768,K=3072): split-K 8 (chunks 384) then reduce -> out row 0
    fgemm2<false, false, EP_STORE><<<dim3(2, 6, 8), 256>>>(
        p_clsh, cw2, p_part, PB, PD, 4 * PD, 4 * PD, PD, PD,
        0, 0, (long long)PB * PD, nullptr, nullptr, nullptr, 0, 384);
    k_reduceK<EP_BIAS><<<(PB * PD + 255) / 256, 256>>>(
        p_part, out, PB * PD, PD, (long long)PB * PD, 8, cb2, 129 * PD);
}

// round 14
// speedup vs baseline: 1.5015x; 1.0220x over previous
#include <cuda_runtime.h>
#include <cuda_bf16.h>
#include <math.h>
#include <cstdint>

// ---------------- problem constants ----------------
#define PB 256
#define PN 128
#define PD 768
#define PE 3
#define PS 44
#define PES 132
#define PESP 136          // padded combine ld
#define PMUP 144          // padded mu_cat ld
#define PH 1024
#define PMAXS 88
#define PM_TOK (PB*PN)
#define PM_FFN (PB*PS)

// ---------------- scratch (device globals) ----------------
__device__ float g_slot_input[PB * 769];
__device__ float g_slot_bias [PB * PD];
__device__ float g_img_n     [PM_TOK * PD];
__device__ float g_dot       [PM_TOK];
__device__ float g_mu_cat    [PD * PMUP];
__device__ float g_logits    [PM_TOK * PES];
__device__ float g_dispT     [PB * PES * PN];     // (b, 132, 128)
__device__ float g_combine   [PM_TOK * PESP];     // padded ld 136
__device__ float g_slot_in   [PB * PES * PD];
__device__ float g_hbuf      [PB * PES * PH];
__device__ float g_slot_out  [PB * PES * PD];
__device__ float g_cls_h     [PB * 4 * PD];
__device__ float g_part      [3 * PB * 4 * PD];   // split-K partials (max: cls1 3x256x3072)

// ---------------- helpers ----------------
__device__ __forceinline__ float gelu_exact(float x) {
    return 0.5f * x * (1.0f + erff(x * 0.70710678118654752440f));
}
__device__ __forceinline__ unsigned long long bcast2(float x) {
    unsigned long long r;
    asm("mov.b64 %0, {%1, %1};" : "=l"(r) : "r"(__float_as_uint(x)));
    return r;
}
__device__ __forceinline__ void ffma2(unsigned long long& c,
                                      unsigned long long a,
                                      unsigned long long b) {
    asm("fma.rn.f32x2 %0, %1, %2, %0;" : "+l"(c) : "l"(a), "l"(b));
}
__device__ __forceinline__ uint32_t smem_u32(const void* p) {
    uint32_t a;
    asm("{ .reg .u64 t; cvta.to.shared.u64 t, %1; cvt.u32.u64 %0, t; }" : "=r"(a) : "l"(p));
    return a;
}
__device__ __forceinline__ void cp_async16(uint32_t dst, const void* src) {
    asm volatile("cp.async.cg.shared.global [%0], [%1], 16;" :: "r"(dst), "l"(src));
}
#define CP_COMMIT() asm volatile("cp.async.commit_group;" ::: "memory")
#define CP_WAIT0()  asm volatile("cp.async.wait_group 0;" ::: "memory")

// ---------------- FFMA2 tiled SGEMM, double-buffered + pipelined ----------------
// C[M,N] = A[M,K] @ B[K,N] row-major; batch via blockIdx.z strides.
// MAP_ROWS: row m -> (m/44)*132 + z*44 + m%44 on A & C (expert slicing).
// kChunk > 0: split-K mode — blockIdx.z selects K range; partial C at z*sC.
#define EP_STORE     0
#define EP_BIAS      1
#define EP_BIAS_GELU 2
#define EP_LOGITS    3

// tile: BM=128, BN=128, BK=16; 256 threads; thread tile 8x8.
template<bool GUARD, bool MAP_ROWS, int EP>
__global__ __launch_bounds__(256)
void fgemm2(const float* __restrict__ A, const float* __restrict__ B,
            float* __restrict__ C,
            int M, int N, int K, int lda, int ldb, int ldc,
            long long sA, long long sB, long long sC,
            const float* __restrict__ v1, const float* __restrict__ v2,
            const float* __restrict__ scale_ptr, int biasStride,
            int kChunk)
{
    const int z = blockIdx.z;
    const float* Ab = A + (long long)z * sA;
    const float* Bb = B + (long long)z * sB;
    float*       Cb = C + (long long)z * sC;

    int ks = 0, ke = K;
    if (kChunk > 0) {
        ks = z * kChunk;
        ke = (K < ks + kChunk) ? K : (ks + kChunk);
    }

    __shared__ __align__(16) float As[2][16][128];
    __shared__ __align__(16) float Bs[2][16][128];

    const int tid = threadIdx.x;          // 256
    const int tx = tid & 15;
    const int ty = tid >> 4;
    const int m0 = blockIdx.x * 128;
    const int n0 = blockIdx.y * 128;

    unsigned long long acc[8][4];
    #pragma unroll
    for (int i = 0; i < 8; i++)
        #pragma unroll
        for (int p = 0; p < 4; p++) acc[i][p] = 0ull;

    // A loader: row tid>>1, k-half (tid&1)*8. B loader: k tid>>4, cols (tid&15)*8.
    const int a_r  = tid >> 1;
    const int a_c8 = (tid & 1) * 8;
    const int t_k = tid >> 4;
    const int t_c = (tid & 15) * 8;

    long long a_off = 0;
    bool a_ok = true;
    {
        const int gm = m0 + a_r;
        a_ok = !GUARD || (gm < M);
        int rr = gm;
        if (MAP_ROWS) rr = (gm / 44) * PES + z * PS + (gm % 44);
        a_off = (long long)rr * lda;
    }
    const bool aAlign = ((a_off & 3) == 0);
    const bool bColsOk = !GUARD || (n0 + 128 <= N);

    // cp.async destinations for B (fast path)
    const uint32_t bsu0 = smem_u32(&Bs[0][t_k][t_c]);
    const uint32_t bsu1 = smem_u32(&Bs[1][t_k][t_c]);

    const int nk = (ke - ks + 15) >> 4;
    float va[8], vb[8];

    // k0 = absolute K base of the 16-wide tile
    auto load_a = [&](int k0) {
        const bool kfull = !GUARD || (k0 + 16 <= ke);
        if ((!GUARD) || (a_ok && aAlign && kfull)) {
            const float4 u0 = *reinterpret_cast<const float4*>(Ab + a_off + k0 + a_c8);
            const float4 u1 = *reinterpret_cast<const float4*>(Ab + a_off + k0 + a_c8 + 4);
            va[0]=u0.x; va[1]=u0.y; va[2]=u0.z; va[3]=u0.w;
            va[4]=u1.x; va[5]=u1.y; va[6]=u1.z; va[7]=u1.w;
        } else {
            #pragma unroll
            for (int j = 0; j < 8; j++) {
                const int k = k0 + a_c8 + j;
                va[j] = (a_ok && k < ke) ? Ab[a_off + k] : 0.f;
            }
        }
    };
    auto store_a = [&](int buf) {
        #pragma unroll
        for (int j = 0; j < 8; j++) As[buf][a_c8 + j][a_r] = va[j];
    };
    auto load_b_guard = [&](int k0) {
        const int gk = k0 + t_k;
        const long long ro = (long long)gk * ldb + n0 + t_c;
        if ((gk < ke) && bColsOk && ((ro & 3) == 0)) {
            const float4 u0 = *reinterpret_cast<const float4*>(Bb + ro);
            const float4 u1 = *reinterpret_cast<const float4*>(Bb + ro + 4);
            vb[0]=u0.x; vb[1]=u0.y; vb[2]=u0.z; vb[3]=u0.w;
            vb[4]=u1.x; vb[5]=u1.y; vb[6]=u1.z; vb[7]=u1.w;
        } else {
            #pragma unroll
            for (int j = 0; j < 8; j++) {
                const int gn = n0 + t_c + j;
                vb[j] = (gk < ke && gn < N) ? Bb[(long long)gk * ldb + gn] : 0.f;
            }
        }
    };
    auto store_b_guard = [&](int buf) {
        *reinterpret_cast<float4*>(&Bs[buf][t_k][t_c])     = make_float4(vb[0], vb[1], vb[2], vb[3]);
        *reinterpret_cast<float4*>(&Bs[buf][t_k][t_c + 4]) = make_float4(vb[4], vb[5], vb[6], vb[7]);
    };
    auto cp_b = [&](int k0, int buf) {
        const int gk = k0 + t_k;
        const float* src = Bb + (long long)gk * ldb + n0 + t_c;
        const uint32_t d = buf ? bsu1 : bsu0;
        cp_async16(d, src);
        cp_async16(d + 16, src + 4);
    };

    // ---- prologue: tile 0 ----
    load_a(ks);
    if (GUARD) {
        load_b_guard(ks);
        store_a(0);
        store_b_guard(0);
    } else {
        cp_b(ks, 0);
        CP_COMMIT();
        store_a(0);
        CP_WAIT0();
    }
    __syncthreads();

    for (int kt = 0; kt < nk; kt++) {
        const int cur = kt & 1;
        const bool more = (kt + 1 < nk);
        if (more) {
            const int k0n = ks + ((kt + 1) << 4);
            if (!GUARD) { cp_b(k0n, cur ^ 1); CP_COMMIT(); }
            else load_b_guard(k0n);
            load_a(k0n);
        }
        // ---- compute from buf cur, register-pipelined fragments ----
        // b-major FMA order: 8 consecutive FFMA2 share one b operand register
        // (same slot, same reg, back-to-back -> operand reuse cache).
        float4 ca0 = *reinterpret_cast<const float4*>(&As[cur][0][ty * 8]);
        float4 ca1 = *reinterpret_cast<const float4*>(&As[cur][0][ty * 8 + 4]);
        ulonglong2 cbl = *reinterpret_cast<const ulonglong2*>(&Bs[cur][0][tx * 4]);
        ulonglong2 cbh = *reinterpret_cast<const ulonglong2*>(&Bs[cur][0][64 + tx * 4]);
        #pragma unroll
        for (int k = 0; k < 16; k++) {
            const int kn = (k + 1) & 15;
            const float4 na0 = *reinterpret_cast<const float4*>(&As[cur][kn][ty * 8]);
            const float4 na1 = *reinterpret_cast<const float4*>(&As[cur][kn][ty * 8 + 4]);
            const ulonglong2 nbl = *reinterpret_cast<const ulonglong2*>(&Bs[cur][kn][tx * 4]);
            const ulonglong2 nbh = *reinterpret_cast<const ulonglong2*>(&Bs[cur][kn][64 + tx * 4]);
            unsigned long long ap[8];
            ap[0] = bcast2(ca0.x); ap[1] = bcast2(ca0.y);
            ap[2] = bcast2(ca0.z); ap[3] = bcast2(ca0.w);
            ap[4] = bcast2(ca1.x); ap[5] = bcast2(ca1.y);
            ap[6] = bcast2(ca1.z); ap[7] = bcast2(ca1.w);
            #pragma unroll
            for (int i = 0; i < 8; i++) ffma2(acc[i][0], ap[i], cbl.x);
            #pragma unroll
            for (int i = 0; i < 8; i++) ffma2(acc[i][1], ap[i], cbl.y);
            #pragma unroll
            for (int i = 0; i < 8; i++) ffma2(acc[i][2], ap[i], cbh.x);
            #pragma unroll
            for (int i = 0; i < 8; i++) ffma2(acc[i][3], ap[i], cbh.y);
            ca0 = na0; ca1 = na1; cbl = nbl; cbh = nbh;
        }
        if (more) {
            store_a(cur ^ 1);
            if (GUARD) store_b_guard(cur ^ 1);
            else CP_WAIT0();
            __syncthreads();
        }
    }

    // ---- epilogue ----
    #pragma unroll
    for (int i = 0; i < 8; i++) {
        const int gm = m0 + ty * 8 + i;
        if (GUARD && gm >= M) continue;
        int rr = gm;
        if (MAP_ROWS) rr = (gm / 44) * PES + z * PS + (gm % 44);
        float dd = 0.f, sc = 0.f; int sel = 0;
        if (EP == EP_LOGITS) {
            const float w = v1[gm];
            sel = (w > 0.7f) ? 0 : ((w >= 0.3f) ? 1 : 2);
            dd = v2[gm];
            sc = scale_ptr[0];
        }
        float* crow = Cb + (long long)rr * ldc;
        #pragma unroll
        for (int p = 0; p < 4; p++) {
            const int gn0 = n0 + ((p < 2) ? (tx * 4 + p * 2) : (64 + tx * 4 + (p - 2) * 2));
            const uint2 u = *reinterpret_cast<const uint2*>(&acc[i][p]);
            #pragma unroll
            for (int h = 0; h < 2; h++) {
                const int gn = gn0 + h;
                if (GUARD && gn >= N) continue;
                float v = __uint_as_float(h ? u.y : u.x);
                if (EP == EP_BIAS) {
                    v += v1[z * biasStride + gn];
                } else if (EP == EP_BIAS_GELU) {
                    v = gelu_exact(v + v1[z * biasStride + gn]);
                } else if (EP == EP_LOGITS) {
                    v = ((gn / PS) == sel) ? sc * (v + dd) : 0.f;
                }
                crow[gn] = v;
            }
        }
    }
}

// ---------------- split-K reduce: out = sum_z part[z] (+bias) (+gelu) ----------------
template<int EP>
__global__ void k_reduceK(const float* __restrict__ part, float* __restrict__ out,
                          int total, int N, long long stride, int nz,
                          const float* __restrict__ bias, int ldcOut)
{
    const int i = blockIdx.x * 256 + threadIdx.x;
    if (i >= total) return;
    float s = 0.f;
    for (int zz = 0; zz < nz; zz++) s += part[(long long)zz * stride + i];
    const int col = i % N;
    if (EP == EP_BIAS)           s += bias[col];
    else if (EP == EP_BIAS_GELU) s = gelu_exact(s + bias[col]);
    out[(long long)(i / N) * ldcOut + col] = s;
}

// ---------------- logits tail: cols 128..131 (expert 2, slots 40..43) ----------------
__global__ void k_logits_tail(const float* __restrict__ img_n,
                              const float* __restrict__ mu_cat,
                              const float* __restrict__ attn,
                              const float* __restrict__ dot,
                              const float* __restrict__ scale_ptr,
                              float* __restrict__ logits)
{
    const int row = blockIdx.x * 8 + (threadIdx.x >> 5);
    const int l = threadIdx.x & 31;
    float* orow = logits + (long long)row * PES + 128;
    const float w = attn[row];
    if (!(w < 0.3f)) {            // expert sel != 2 -> masked to exact 0
        if (l < 4) orow[l] = 0.f;
        return;
    }
    const float* a = img_n + (long long)row * PD;
    float a0 = 0.f, a1 = 0.f, a2 = 0.f, a3 = 0.f;
    for (int k = l; k < PD; k += 32) {
        const float av = a[k];
        const float* mrow = mu_cat + k * PMUP + 128;
        a0 += av * mrow[0];
        a1 += av * mrow[1];
        a2 += av * mrow[2];
        a3 += av * mrow[3];
    }
    for (int o = 16; o; o >>= 1) {
        a0 += __shfl_xor_sync(~0u, a0, o);
        a1 += __shfl_xor_sync(~0u, a1, o);
        a2 += __shfl_xor_sync(~0u, a2, o);
        a3 += __shfl_xor_sync(~0u, a3, o);
    }
    if (l == 0) {
        const float sc = scale_ptr[0];
        const float dd = dot[row];
        orow[0] = sc * (a0 + dd);
        orow[1] = sc * (a1 + dd);
        orow[2] = sc * (a2 + dd);
        orow[3] = sc * (a3 + dd);
    }
}

// ---------------- slot_in tail: rows 128..131 per batch ----------------
__global__ void k_slotin_tail(const float* __restrict__ dispT,
                              const float* __restrict__ x,
                              float* __restrict__ slot_in)
{
    const int b = blockIdx.x;
    const int t = threadIdx.x;   // 256
    const float* img = x + (long long)b * 129 * PD + PD;
    const float* wrow = dispT + (long long)b * PES * PN + 128 * PN;
    __shared__ float wsh[4][PN];
    for (int i = t; i < 4 * PN; i += 256) wsh[i >> 7][i & 127] = wrow[i];
    __syncthreads();
    for (int d = t; d < PD; d += 256) {
        float a0 = 0.f, a1 = 0.f, a2 = 0.f, a3 = 0.f;
        #pragma unroll 4
        for (int n = 0; n < PN; n++) {
            const float v = img[(long long)n * PD + d];
            a0 += wsh[0][n] * v;
            a1 += wsh[1][n] * v;
            a2 += wsh[2][n] * v;
            a3 += wsh[3][n] * v;
        }
        float* o = slot_in + (long long)b * PES * PD + (long long)128 * PD + d;
        o[0]      = a0;
        o[PD]     = a1;
        o[2 * PD] = a2;
        o[3 * PD] = a3;
    }
}

// ---------------- mu rearrange (padded ld 144) ----------------
__global__ void k_prep_mu(const float* __restrict__ mu, float* __restrict__ mu_cat) {
    int idx = blockIdx.x * blockDim.x + threadIdx.x;
    if (idx >= PD * PES) return;
    int d = idx / PES, j = idx % PES;
    int e = j / PS, s = j % PS;
    mu_cat[d * PMUP + j] = mu[((long long)e * PD + d) * PMAXS + s];
}

// ---------------- slot_input = [cls, mean(attn)] ----------------
__global__ void k_build_slotinput(const float* __restrict__ x,
                                  const float* __restrict__ attn,
                                  float* __restrict__ si) {
    int b = blockIdx.x;
    int t = threadIdx.x;
    __shared__ float red[8];
    float s = (t < PN) ? attn[b * PN + t] : 0.f;
    for (int o = 16; o; o >>= 1) s += __shfl_xor_sync(~0u, s, o);
    if ((t & 31) == 0) red[t >> 5] = s;
    __syncthreads();
    const float* cls = x + (long long)b * 129 * PD;
    float* o = si + (long long)b * 769;
    for (int d = t; d < PD; d += 256) o[d] = cls[d];
    if (t == 0) {
        float m = 0.f;
        #pragma unroll
        for (int i = 0; i < 8; i++) m += red[i];
        o[PD] = m * (1.f / (float)PN);
    }
}

// ---------------- LayerNorm + dot ----------------
__global__ void k_ln_dot(const float* __restrict__ x,
                         const float* __restrict__ gamma,
                         const float* __restrict__ beta,
                         const float* __restrict__ slot_bias,
                         float* __restrict__ img_n,
                         float* __restrict__ dot) {
    const int m = blockIdx.x;
    const int b = m >> 7;
    const int n = m & 127;
    const float* row = x + ((long long)b * 129 + 1 + n) * PD;
    const int t = threadIdx.x;
    const int w = t >> 5, l = t & 31;
    __shared__ float rs[8], rq[8];

    float v[3], s = 0.f, sq = 0.f;
    #pragma unroll
    for (int i = 0; i < 3; i++) {
        v[i] = row[t + i * 256];
        s += v[i];
        sq += v[i] * v[i];
    }
    for (int o = 16; o; o >>= 1) {
        s  += __shfl_xor_sync(~0u, s, o);
        sq += __shfl_xor_sync(~0u, sq, o);
    }
    if (l == 0) { rs[w] = s; rq[w] = sq; }
    __syncthreads();
    float ts = 0.f, tq = 0.f;
    #pragma unroll
    for (int i = 0; i < 8; i++) { ts += rs[i]; tq += rq[i]; }
    const float mean = ts * (1.f / (float)PD);
    const float var  = tq * (1.f / (float)PD) - mean * mean;
    const float inv  = rsqrtf(var + 1e-5f);
    __syncthreads();

    const float* sb = slot_bias + (long long)b * PD;
    float* orow = img_n + (long long)m * PD;
    float dp = 0.f;
    #pragma unroll
    for (int i = 0; i < 3; i++) {
        const int d = t + i * 256;
        const float y = (v[i] - mean) * inv * gamma[d] + beta[d];
        orow[d] = y;
        dp += y * sb[d];
    }
    for (int o = 16; o; o >>= 1) dp += __shfl_xor_sync(~0u, dp, o);
    if (l == 0) rs[w] = dp;
    __syncthreads();
    if (t == 0) {
        float d2 = 0.f;
        #pragma unroll
        for (int i = 0; i < 8; i++) d2 += rs[i];
        dot[m] = d2;
    }
}

// ---------------- dispatch softmax -> transposed output ----------------
__global__ void k_dispatch(const float* __restrict__ logits, float* __restrict__ dispT) {
    const int be = blockIdx.x;
    const int b = be / PE, e = be % PE;
    __shared__ float tile[PN][PS];
    __shared__ float csum[PS];
    const int t = threadIdx.x;
    const float* base = logits + (long long)b * PN * PES + e * PS;
    for (int idx = t; idx < PN * PS; idx += 256) {
        const int n = idx / PS, j = idx % PS;
        tile[n][j] = base[(long long)n * PES + j];
    }
    __syncthreads();
    if (t < PS) {
        float mx = -1e30f;
        for (int n = 0; n < PN; n++) mx = fmaxf(mx, tile[n][t]);
        float sm = 0.f;
        for (int n = 0; n < PN; n++) {
            const float ev = expf(tile[n][t] - mx);
            tile[n][t] = ev;
            sm += ev;
        }
        csum[t] = sm;
    }
    __syncthreads();
    float* ob = dispT + (long long)b * PES * PN + (long long)e * PS * PN;
    for (int idx = t; idx < PN * PS; idx += 256) {
        const int j = idx >> 7, n = idx & 127;
        ob[j * PN + n] = tile[n][j] / csum[j];
    }
}

// ---------------- combine softmax (padded ld out) ----------------
__global__ void k_combine(const float* __restrict__ logits, float* __restrict__ comb) {
    const int row = blockIdx.x * 8 + (threadIdx.x >> 5);
    const int l = threadIdx.x & 31;
    if (row >= PM_TOK) return;
    const float* r = logits + (long long)row * PES;
    float vals[5], mx = -1e30f;
    #pragma unroll
    for (int i = 0; i < 5; i++) {
        const int j = l + i * 32;
        vals[i] = (j < PES) ? r[j] : -1e30f;
        mx = fmaxf(mx, vals[i]);
    }
    for (int o = 16; o; o >>= 1) mx = fmaxf(mx, __shfl_xor_sync(~0u, mx, o));
    float s = 0.f;
    #pragma unroll
    for (int i = 0; i < 5; i++) {
        const int j = l + i * 32;
        if (j < PES) { vals[i] = expf(vals[i] - mx); s += vals[i]; }
    }
    for (int o = 16; o; o >>= 1) s += __shfl_xor_sync(~0u, s, o);
    const float inv = 1.f / s;
    float* o = comb + (long long)row * PESP;
    #pragma unroll
    for (int i = 0; i < 5; i++) {
        const int j = l + i * 32;
        if (j < PES) o[j] = vals[i] * inv;
    }
}

// ---------------- launch ----------------
extern "C" void kernel_launch(void* const* d_in, const int* in_sizes, int n_in,
                              void* d_out, int out_size) {
    const float* x      = (const float*)d_in[0];
    const float* attn   = (const float*)d_in[1];
    const float* gamma  = (const float*)d_in[2];
    const float* beta   = (const float*)d_in[3];
    const float* vsg_w  = (const float*)d_in[4];
    const float* vsg_b  = (const float*)d_in[5];
    const float* mu     = (const float*)d_in[6];
    const float* scale  = (const float*)d_in[7];
    const float* w1     = (const float*)d_in[8];
    const float* b1     = (const float*)d_in[9];
    const float* w2     = (const float*)d_in[10];
    const float* b2     = (const float*)d_in[11];
    const float* cw1    = (const float*)d_in[12];
    const float* cb1    = (const float*)d_in[13];
    const float* cw2    = (const float*)d_in[14];
    const float* cb2    = (const float*)d_in[15];
    float* out = (float*)d_out;

    float *p_si, *p_sb, *p_imgn, *p_dot, *p_mu, *p_log, *p_dispT, *p_comb;
    float *p_sin, *p_h, *p_sout, *p_clsh, *p_part;
    cudaGetSymbolAddress((void**)&p_si,    g_slot_input);
    cudaGetSymbolAddress((void**)&p_sb,    g_slot_bias);
    cudaGetSymbolAddress((void**)&p_imgn,  g_img_n);
    cudaGetSymbolAddress((void**)&p_dot,   g_dot);
    cudaGetSymbolAddress((void**)&p_mu,    g_mu_cat);
    cudaGetSymbolAddress((void**)&p_log,   g_logits);
    cudaGetSymbolAddress((void**)&p_dispT, g_dispT);
    cudaGetSymbolAddress((void**)&p_comb,  g_combine);
    cudaGetSymbolAddress((void**)&p_sin,   g_slot_in);
    cudaGetSymbolAddress((void**)&p_h,     g_hbuf);
    cudaGetSymbolAddress((void**)&p_sout,  g_slot_out);
    cudaGetSymbolAddress((void**)&p_clsh,  g_cls_h);
    cudaGetSymbolAddress((void**)&p_part,  g_part);

    // 1. mu -> (768, 144-padded 132)
    k_prep_mu<<<(PD * PES + 255) / 256, 256>>>(mu, p_mu);
    // 2. slot_input
    k_build_slotinput<<<PB, 256>>>(x, attn, p_si);
    // 3. slot_bias: split-K 4 (chunks of 208; last 145) then reduce + bias
    fgemm2<true, false, EP_STORE><<<dim3(2, 6, 4), 256>>>(
        p_si, vsg_w, p_part, PB, PD, 769, 769, PD, PD,
        0, 0, (long long)PB * PD, nullptr, nullptr, nullptr, 0, 208);
    k_reduceK<EP_BIAS><<<(PB * PD + 255) / 256, 256>>>(
        p_part, p_sb, PB * PD, PD, (long long)PB * PD, 4, vsg_b, PD);
    // 4. LayerNorm + dot
    k_ln_dot<<<PM_TOK, 256>>>(x, gamma, beta, p_sb, p_imgn, p_dot);
    // 5. logits cols 0..127 (32768,128,K=768), cols 128..131 via tail kernel
    fgemm2<true, false, EP_LOGITS><<<dim3(PM_TOK / 128, 1, 1), 256>>>(
        p_imgn, p_mu, p_log, PM_TOK, PES, PD, PD, PMUP, PES,
        0, 0, 0, attn, p_dot, scale, 0, 0);
    k_logits_tail<<<PM_TOK / 8, 256>>>(p_imgn, p_mu, attn, p_dot, scale, p_log);
    // 6/7. softmaxes
    k_dispatch<<<PB * PE, 256>>>(p_log, p_dispT);
    k_combine<<<PM_TOK / 8, 256>>>(p_log, p_comb);
    // 8. slot_in rows 0..127 (128,768,K=128) batched; rows 128..131 via tail
    fgemm2<true, false, EP_STORE><<<dim3(1, 6, PB), 256>>>(
        p_dispT, x + PD, p_sin, PES, PD, PN, PN, PD, PD,
        (long long)PES * PN, (long long)129 * PD, (long long)PES * PD,
        nullptr, nullptr, nullptr, 0, 0);
    k_slotin_tail<<<PB, 256>>>(p_dispT, x, p_sin);
    // 9. FFN1 (11264,1024,K=768) per expert
    fgemm2<false, true, EP_BIAS_GELU><<<dim3(PM_FFN / 128, PH / 128, PE), 256>>>(
        p_sin, w1, p_h, PM_FFN, PH, PD, PD, PH, PH,
        0, (long long)PD * PH, 0, b1, nullptr, nullptr, PH, 0);
    // 10. FFN2 (11264,768,K=1024) per expert
    fgemm2<false, true, EP_BIAS><<<dim3(PM_FFN / 128, PD / 128, PE), 256>>>(
        p_h, w2, p_sout, PM_FFN, PD, PH, PH, PD, PD,
        0, (long long)PH * PD, 0, b2, nullptr, nullptr, PD, 0);
    // 11. img_out[b] = combine[b] @ slot_out[b]  (128,768,K=132) batched
    fgemm2<true, false, EP_STORE><<<dim3(1, 6, PB), 256>>>(
        p_comb, p_sout, out + PD, PN, PD, PES, PESP, PD, PD,
        (long long)PN * PESP, (long long)PES * PD, (long long)129 * PD,
        nullptr, nullptr, nullptr, 0, 0);
    // 12. cls1 (256,3072,K=768): split-K 3 (chunks 256) then reduce + bias + gelu
    fgemm2<false, false, EP_STORE><<<dim3(2, 24, 3), 256>>>(
        x, cw1, p_part, PB, 4 * PD, PD, 129 * PD, 4 * PD, 4 * PD,
        0, 0, (long long)PB * 4 * PD, nullptr, nullptr, nullptr, 0, 256);
    k_reduceK<EP_BIAS_GELU><<<(PB * 4 * PD + 255) / 256, 256>>>(
        p_part, p_clsh, PB * 4 * PD, 4 * PD, (long long)PB * 4 * PD, 3, cb1, 4 * PD);
    // 13. cls2 (256,768,K=3072): split-K 8 (chunks 384) then reduce -> out row 0
    fgemm2<false, false, EP_STORE><<<dim3(2, 6, 8), 256>>>(
        p_clsh, cw2, p_part, PB, PD, 4 * PD, 4 * PD, PD, PD,
        0, 0, (long long)PB * PD, nullptr, nullptr, nullptr, 0, 384);
    k_reduceK<EP_BIAS><<<(PB * PD + 255) / 256, 256>>>(
        p_part, out, PB * PD, PD, (long long)PB * PD, 8, cb2, 129 * PD);
}